// round 1
// baseline (speedup 1.0000x reference)
#include <cuda_runtime.h>

// Problem constants
#define B_  16
#define T_  2048
#define C_  1024
#define H_  64

// Scratch for q, k, v: [B, T, H] fp32 each (8 MB each) — __device__ globals,
// no allocation (allowed per harness rules).
__device__ float g_q[(size_t)B_ * T_ * H_];
__device__ float g_k[(size_t)B_ * T_ * H_];
__device__ float g_v[(size_t)B_ * T_ * H_];

// ---------------------------------------------------------------------------
// Kernel 1: fused QKV projection. out = x[32768,1024] @ W[1024,64]
// Tile: BM=128 rows, BN=64 cols (full H), BK=16. 256 threads, 8x4 microtile.
// blockIdx.y selects {Wq (scaled by H^-0.5), Wk, Wv}.
// ---------------------------------------------------------------------------
__global__ __launch_bounds__(256) void proj_kernel(
    const float* __restrict__ x,
    const float* __restrict__ Wq,
    const float* __restrict__ Wk,
    const float* __restrict__ Wv)
{
    const int which = blockIdx.y;
    const float* __restrict__ W = (which == 0) ? Wq : ((which == 1) ? Wk : Wv);
    float* __restrict__ out = (which == 0) ? g_q : ((which == 1) ? g_k : g_v);

    const int row0 = blockIdx.x * 128;
    const int tid = threadIdx.x;
    const int ty = tid >> 4;   // 0..15  -> 8-row group
    const int tx = tid & 15;   // 0..15  -> 4-col group

    __shared__ float As[16][128];   // [k][m], transposed on load
    __shared__ float Bs[16][64];    // [k][n]

    float acc[8][4];
#pragma unroll
    for (int j = 0; j < 8; j++)
#pragma unroll
        for (int jj = 0; jj < 4; jj++) acc[j][jj] = 0.f;

    for (int k0 = 0; k0 < C_; k0 += 16) {
        // Load A tile (128x16): 2048 elems / 256 thr = 8 each, coalesced in k.
#pragma unroll
        for (int i = 0; i < 8; i++) {
            int idx = tid + i * 256;
            int m = idx >> 4;
            int k = idx & 15;
            As[k][m] = x[(size_t)(row0 + m) * C_ + k0 + k];
        }
        // Load B tile (16x64): 1024 elems / 256 thr = 4 each, coalesced in n.
#pragma unroll
        for (int i = 0; i < 4; i++) {
            int idx = tid + i * 256;
            int k = idx >> 6;
            int n = idx & 63;
            Bs[k][n] = W[(size_t)(k0 + k) * H_ + n];
        }
        __syncthreads();

#pragma unroll
        for (int kk = 0; kk < 16; kk++) {
            float a[8], bf[4];
#pragma unroll
            for (int j = 0; j < 8; j++) a[j] = As[kk][ty * 8 + j];
#pragma unroll
            for (int jj = 0; jj < 4; jj++) bf[jj] = Bs[kk][tx * 4 + jj];
#pragma unroll
            for (int j = 0; j < 8; j++)
#pragma unroll
                for (int jj = 0; jj < 4; jj++)
                    acc[j][jj] += a[j] * bf[jj];
        }
        __syncthreads();
    }

    const float scale = (which == 0) ? 0.125f : 1.0f;  // 64^-0.5 folded into q
#pragma unroll
    for (int j = 0; j < 8; j++)
#pragma unroll
        for (int jj = 0; jj < 4; jj++)
            out[(size_t)(row0 + ty * 8 + j) * H_ + tx * 4 + jj] = acc[j][jj] * scale;
}

// ---------------------------------------------------------------------------
// Kernel 2: causal flash attention.
// One thread per query row. BM=64 queries/block (64 threads), key tiles BS=32.
// q[64] and o[64] live in registers (float4[16]); K/V tiles in smem (broadcast
// reads); per-thread score buffer in smem padded to stride 33 (conflict-free).
// ---------------------------------------------------------------------------
#define BM 64
#define BS 32

__global__ __launch_bounds__(BM) void attn_kernel(float* __restrict__ out)
{
    const int b   = blockIdx.y;
    const int qt0 = blockIdx.x * BM;
    const int tid = threadIdx.x;
    const int t   = qt0 + tid;

    __shared__ float Ks[BS][H_];
    __shared__ float Vs[BS][H_];
    __shared__ float Sb[BM][BS + 1];   // stride 33 -> no bank conflicts

    const float* __restrict__ qptr = g_q + ((size_t)b * T_ + t) * H_;
    float4 q4[16];
#pragma unroll
    for (int i = 0; i < 16; i++)
        q4[i] = reinterpret_cast<const float4*>(qptr)[i];

    float4 o4[16];
#pragma unroll
    for (int i = 0; i < 16; i++) o4[i] = make_float4(0.f, 0.f, 0.f, 0.f);
    float mrun = -1e30f, lrun = 0.f;

    const float* __restrict__ kbase = g_k + (size_t)b * T_ * H_;
    const float* __restrict__ vbase = g_v + (size_t)b * T_ * H_;

    const int s_end = qt0 + BM;   // causal: no keys beyond the query tile
    for (int s0 = 0; s0 < s_end; s0 += BS) {
        // Cooperative K/V tile load: BS*H_ = 2048 floats = 512 float4; 8/thread.
#pragma unroll
        for (int i = 0; i < 8; i++) {
            int idx = tid + i * BM;
            reinterpret_cast<float4*>(&Ks[0][0])[idx] =
                reinterpret_cast<const float4*>(kbase + (size_t)s0 * H_)[idx];
            reinterpret_cast<float4*>(&Vs[0][0])[idx] =
                reinterpret_cast<const float4*>(vbase + (size_t)s0 * H_)[idx];
        }
        __syncthreads();

        // Pass 1: scores + tile max (scale already folded into q).
        float tmax = -1e30f;
#pragma unroll 4
        for (int j = 0; j < BS; j++) {
            const float4* krow = reinterpret_cast<const float4*>(&Ks[j][0]);
            float s = 0.f;
#pragma unroll
            for (int i = 0; i < 16; i++) {
                float4 kv = krow[i];
                s += q4[i].x * kv.x + q4[i].y * kv.y
                   + q4[i].z * kv.z + q4[i].w * kv.w;
            }
            s = (s0 + j <= t) ? s : -1e30f;
            Sb[tid][j] = s;
            tmax = fmaxf(tmax, s);
        }

        // Online-softmax rescale.
        const float newm = fmaxf(mrun, tmax);
        const float alpha = __expf(mrun - newm);
        lrun *= alpha;
#pragma unroll
        for (int i = 0; i < 16; i++) {
            o4[i].x *= alpha; o4[i].y *= alpha;
            o4[i].z *= alpha; o4[i].w *= alpha;
        }

        // Pass 2: p = exp(s - newm), accumulate o += p * V[j].
#pragma unroll 2
        for (int j = 0; j < BS; j++) {
            float p = __expf(Sb[tid][j] - newm);
            lrun += p;
            const float4* vrow = reinterpret_cast<const float4*>(&Vs[j][0]);
#pragma unroll
            for (int i = 0; i < 16; i++) {
                float4 vv = vrow[i];
                o4[i].x += p * vv.x; o4[i].y += p * vv.y;
                o4[i].z += p * vv.z; o4[i].w += p * vv.w;
            }
        }
        mrun = newm;
        __syncthreads();
    }

    const float inv = 1.f / lrun;
    float* __restrict__ optr = out + ((size_t)b * T_ + t) * H_;
#pragma unroll
    for (int i = 0; i < 16; i++) {
        float4 v = o4[i];
        v.x *= inv; v.y *= inv; v.z *= inv; v.w *= inv;
        reinterpret_cast<float4*>(optr)[i] = v;
    }
}

// ---------------------------------------------------------------------------
extern "C" void kernel_launch(void* const* d_in, const int* in_sizes, int n_in,
                              void* d_out, int out_size)
{
    const float* x  = (const float*)d_in[0];
    const float* Wq = (const float*)d_in[1];
    const float* Wk = (const float*)d_in[2];
    const float* Wv = (const float*)d_in[3];
    float* out = (float*)d_out;

    // QKV projection: M=32768 rows / 128 per block, 3 weight matrices.
    dim3 gproj((B_ * T_) / 128, 3);
    proj_kernel<<<gproj, 256>>>(x, Wq, Wk, Wv);

    // Attention: 32 query tiles x 16 batches = 512 blocks.
    dim3 gattn(T_ / BM, B_);
    attn_kernel<<<gattn, BM>>>(out);
}

// round 2
// speedup vs baseline: 1.1932x; 1.1932x over previous
#include <cuda_runtime.h>

// Problem constants
#define B_  16
#define T_  2048
#define C_  1024
#define H_  64

// Scratch for q, k, v: [B, T, H] fp32 each (8 MB each).
__device__ float g_q[(size_t)B_ * T_ * H_];
__device__ float g_k[(size_t)B_ * T_ * H_];
__device__ float g_v[(size_t)B_ * T_ * H_];

// ---------------------------------------------------------------------------
// Kernel 1: fused QKV projection. {q,k,v} = x[32768,1024] @ {Wq,Wk,Wv}[1024,64]
// One block computes a 64-row stripe for ALL THREE weight matrices (x tile is
// loaded once). BM=64, BK=32, 256 threads, microtile 4 rows x 4 cols x 3 mats.
// ---------------------------------------------------------------------------
__global__ __launch_bounds__(256) void proj_kernel(
    const float* __restrict__ x,
    const float* __restrict__ Wq,
    const float* __restrict__ Wk,
    const float* __restrict__ Wv)
{
    const int row0 = blockIdx.x * 64;
    const int tid = threadIdx.x;
    const int ty = tid >> 4;   // 0..15 -> 4-row group
    const int tx = tid & 15;   // 0..15 -> 4-col group

    __shared__ float As[32][64];      // [k][m]
    __shared__ float Bs[3][32][64];   // [mat][k][n]

    float acc[3][4][4];
#pragma unroll
    for (int m = 0; m < 3; m++)
#pragma unroll
        for (int r = 0; r < 4; r++)
#pragma unroll
            for (int c = 0; c < 4; c++) acc[m][r][c] = 0.f;

    const float* Wmat[3] = {Wq, Wk, Wv};

    for (int k0 = 0; k0 < C_; k0 += 32) {
        // x tile: 64 rows x 32 k = 512 float4, 2 per thread. Stored transposed.
#pragma unroll
        for (int i = 0; i < 2; i++) {
            int idx = tid + i * 256;
            int m = idx >> 3;          // row 0..63
            int kq = idx & 7;          // float4 index within 32 k's
            float4 v = reinterpret_cast<const float4*>(
                x + (size_t)(row0 + m) * C_ + k0)[kq];
            As[kq * 4 + 0][m] = v.x;
            As[kq * 4 + 1][m] = v.y;
            As[kq * 4 + 2][m] = v.z;
            As[kq * 4 + 3][m] = v.w;
        }
        // W tiles: 32 k x 64 n per mat = 512 float4, 2 per thread per mat.
#pragma unroll
        for (int m = 0; m < 3; m++) {
#pragma unroll
            for (int i = 0; i < 2; i++) {
                int idx = tid + i * 256;
                int k = idx >> 4;      // 0..31
                int n4 = idx & 15;     // float4 col group
                float4 v = reinterpret_cast<const float4*>(
                    Wmat[m] + (size_t)(k0 + k) * H_)[n4];
                *reinterpret_cast<float4*>(&Bs[m][k][n4 * 4]) = v;
            }
        }
        __syncthreads();

#pragma unroll
        for (int kk = 0; kk < 32; kk++) {
            float4 av = *reinterpret_cast<const float4*>(&As[kk][ty * 4]);
            float a[4] = {av.x, av.y, av.z, av.w};
#pragma unroll
            for (int m = 0; m < 3; m++) {
                float4 bv = *reinterpret_cast<const float4*>(&Bs[m][kk][tx * 4]);
                float bf[4] = {bv.x, bv.y, bv.z, bv.w};
#pragma unroll
                for (int r = 0; r < 4; r++)
#pragma unroll
                    for (int c = 0; c < 4; c++)
                        acc[m][r][c] += a[r] * bf[c];
            }
        }
        __syncthreads();
    }

    float* outp[3] = {g_q, g_k, g_v};
    const float scl[3] = {0.125f, 1.0f, 1.0f};   // 64^-0.5 folded into q
#pragma unroll
    for (int m = 0; m < 3; m++)
#pragma unroll
        for (int r = 0; r < 4; r++) {
            float4 v;
            v.x = acc[m][r][0] * scl[m];
            v.y = acc[m][r][1] * scl[m];
            v.z = acc[m][r][2] * scl[m];
            v.w = acc[m][r][3] * scl[m];
            reinterpret_cast<float4*>(
                outp[m] + (size_t)(row0 + ty * 4 + r) * H_)[tx] = v;
        }
}

// ---------------------------------------------------------------------------
// Kernel 2: causal flash attention. One thread per query row, BM=64, BS=32.
// q, o, and per-tile scores all in registers; K/V tiles in smem (broadcast).
// Query tiles issued longest-first to fix tail imbalance.
// ---------------------------------------------------------------------------
#define BM 64
#define BS 32

__global__ __launch_bounds__(BM) void attn_kernel(float* __restrict__ out)
{
    const int b   = blockIdx.y;
    const int qt0 = (gridDim.x - 1 - blockIdx.x) * BM;  // longest blocks first
    const int tid = threadIdx.x;
    const int t   = qt0 + tid;

    __shared__ float Ks[BS][H_];
    __shared__ float Vs[BS][H_];

    const float* __restrict__ qptr = g_q + ((size_t)b * T_ + t) * H_;
    float4 q4[16];
#pragma unroll
    for (int i = 0; i < 16; i++)
        q4[i] = reinterpret_cast<const float4*>(qptr)[i];

    float4 o4[16];
#pragma unroll
    for (int i = 0; i < 16; i++) o4[i] = make_float4(0.f, 0.f, 0.f, 0.f);
    float mrun = -1e30f, l0 = 0.f, l1 = 0.f;

    const float* __restrict__ kbase = g_k + (size_t)b * T_ * H_;
    const float* __restrict__ vbase = g_v + (size_t)b * T_ * H_;

    const int s_end = qt0 + BM;
    for (int s0 = 0; s0 < s_end; s0 += BS) {
        // Cooperative K/V tile load: 512 float4 each, 8 per thread.
#pragma unroll
        for (int i = 0; i < 8; i++) {
            int idx = tid + i * BM;
            reinterpret_cast<float4*>(&Ks[0][0])[idx] =
                reinterpret_cast<const float4*>(kbase + (size_t)s0 * H_)[idx];
            reinterpret_cast<float4*>(&Vs[0][0])[idx] =
                reinterpret_cast<const float4*>(vbase + (size_t)s0 * H_)[idx];
        }
        __syncthreads();

        // Pass 1: scores into REGISTERS with 4-way split accumulators.
        float sreg[BS];
        float tmax = -1e30f;
#pragma unroll
        for (int j = 0; j < BS; j++) {
            const float4* krow = reinterpret_cast<const float4*>(&Ks[j][0]);
            float a0 = 0.f, a1 = 0.f, a2 = 0.f, a3 = 0.f;
#pragma unroll
            for (int i = 0; i < 16; i += 4) {
                float4 k0v = krow[i + 0], k1v = krow[i + 1];
                float4 k2v = krow[i + 2], k3v = krow[i + 3];
                a0 += q4[i + 0].x * k0v.x + q4[i + 0].y * k0v.y
                    + q4[i + 0].z * k0v.z + q4[i + 0].w * k0v.w;
                a1 += q4[i + 1].x * k1v.x + q4[i + 1].y * k1v.y
                    + q4[i + 1].z * k1v.z + q4[i + 1].w * k1v.w;
                a2 += q4[i + 2].x * k2v.x + q4[i + 2].y * k2v.y
                    + q4[i + 2].z * k2v.z + q4[i + 2].w * k2v.w;
                a3 += q4[i + 3].x * k3v.x + q4[i + 3].y * k3v.y
                    + q4[i + 3].z * k3v.z + q4[i + 3].w * k3v.w;
            }
            float s = (a0 + a1) + (a2 + a3);
            s = (s0 + j <= t) ? s : -1e30f;
            sreg[j] = s;
            tmax = fmaxf(tmax, s);
        }

        // Online-softmax rescale.
        const float newm = fmaxf(mrun, tmax);
        const float alpha = __expf(mrun - newm);
        l0 *= alpha; l1 *= alpha;
#pragma unroll
        for (int i = 0; i < 16; i++) {
            o4[i].x *= alpha; o4[i].y *= alpha;
            o4[i].z *= alpha; o4[i].w *= alpha;
        }

        // Pass 2: p = exp(s - newm), o += p * V[j].
#pragma unroll
        for (int j = 0; j < BS; j++) {
            float p = __expf(sreg[j] - newm);
            if (j & 1) l1 += p; else l0 += p;
            const float4* vrow = reinterpret_cast<const float4*>(&Vs[j][0]);
#pragma unroll
            for (int i = 0; i < 16; i++) {
                float4 vv = vrow[i];
                o4[i].x += p * vv.x; o4[i].y += p * vv.y;
                o4[i].z += p * vv.z; o4[i].w += p * vv.w;
            }
        }
        mrun = newm;
        __syncthreads();
    }

    const float inv = 1.f / (l0 + l1);
    float* __restrict__ optr = out + ((size_t)b * T_ + t) * H_;
#pragma unroll
    for (int i = 0; i < 16; i++) {
        float4 v = o4[i];
        v.x *= inv; v.y *= inv; v.z *= inv; v.w *= inv;
        reinterpret_cast<float4*>(optr)[i] = v;
    }
}

// ---------------------------------------------------------------------------
extern "C" void kernel_launch(void* const* d_in, const int* in_sizes, int n_in,
                              void* d_out, int out_size)
{
    const float* x  = (const float*)d_in[0];
    const float* Wq = (const float*)d_in[1];
    const float* Wk = (const float*)d_in[2];
    const float* Wv = (const float*)d_in[3];
    float* out = (float*)d_out;

    // Fused QKV projection: 32768 rows / 64 per block = 512 blocks.
    proj_kernel<<<(B_ * T_) / 64, 256>>>(x, Wq, Wk, Wv);

    // Attention: 32 query tiles x 16 batches.
    dim3 gattn(T_ / BM, B_);
    attn_kernel<<<gattn, BM>>>(out);
}

// round 4
// speedup vs baseline: 1.7276x; 1.4479x over previous
#include <cuda_runtime.h>
#include <cuda_bf16.h>
#include <cstdint>

#define B_  16
#define T_  2048
#define C_  1024
#define H_  64

// q/k/v stored pre-split as bf16 hi/lo pairs (hi + lo reconstructs ~fp32/2^-17).
__device__ __nv_bfloat16 g_qh[(size_t)B_ * T_ * H_];
__device__ __nv_bfloat16 g_ql[(size_t)B_ * T_ * H_];
__device__ __nv_bfloat16 g_kh[(size_t)B_ * T_ * H_];
__device__ __nv_bfloat16 g_kl[(size_t)B_ * T_ * H_];
__device__ __nv_bfloat16 g_vh[(size_t)B_ * T_ * H_];
__device__ __nv_bfloat16 g_vl[(size_t)B_ * T_ * H_];

// ---------------------------------------------------------------------------
// mma.sync m16n8k16 bf16 (sm_80+ baseline — works on sm_103 target).
// A row-major, B col-major, fp32 accum.
// ---------------------------------------------------------------------------
__device__ __forceinline__ void mma_bf16(float* d, const uint32_t* a,
                                         const uint32_t* b) {
    asm volatile(
        "mma.sync.aligned.m16n8k16.row.col.f32.bf16.bf16.f32 "
        "{%0,%1,%2,%3}, {%4,%5,%6,%7}, {%8,%9}, {%0,%1,%2,%3};"
        : "+f"(d[0]), "+f"(d[1]), "+f"(d[2]), "+f"(d[3])
        : "r"(a[0]), "r"(a[1]), "r"(a[2]), "r"(a[3]), "r"(b[0]), "r"(b[1]));
}

__device__ __forceinline__ void ldsm_x2_trans(uint32_t& r0, uint32_t& r1,
                                              uint32_t addr) {
    asm volatile("ldmatrix.sync.aligned.m8n8.x2.trans.shared.b16 {%0,%1}, [%2];"
                 : "=r"(r0), "=r"(r1) : "r"(addr));
}

__device__ __forceinline__ uint32_t smem_u32(const void* p) {
    uint32_t a;
    asm("{ .reg .u64 t; cvta.to.shared.u64 t, %1; cvt.u32.u64 %0, t; }"
        : "=r"(a) : "l"(p));
    return a;
}

// Split (x,y) into packed bf16x2 hi and lo (residual) words.
__device__ __forceinline__ void split_pair(float x, float y,
                                           uint32_t& hi, uint32_t& lo) {
    __nv_bfloat16 hx = __float2bfloat16(x);
    __nv_bfloat16 hy = __float2bfloat16(y);
    __nv_bfloat162 hv(hx, hy);
    hi = *reinterpret_cast<uint32_t*>(&hv);
    __nv_bfloat162 lv = __floats2bfloat162_rn(x - __bfloat162float(hx),
                                              y - __bfloat162float(hy));
    lo = *reinterpret_cast<uint32_t*>(&lv);
}

// ===========================================================================
// Kernel 1: QKV projection (tensor core).
// C[64 rows][192 cols] per block, cols = {q|k|v} x 64. BK=32, 384 threads:
// 2 m-warps x 6 n-warps; each warp: 2 m16-tiles x 4 n8-tiles, split x3.
// ===========================================================================
#define PSTR 36   // smem k-stride (padding -> conflict-free frag LDS)

__global__ __launch_bounds__(384) void proj_kernel(
    const float* __restrict__ x,
    const float* __restrict__ Wq,
    const float* __restrict__ Wk,
    const float* __restrict__ Wv)
{
    __shared__ __nv_bfloat16 Xh[64][PSTR],  Xl[64][PSTR];
    __shared__ __nv_bfloat16 Wh[192][PSTR], Wl[192][PSTR];

    const int tid = threadIdx.x;
    const int wid = tid >> 5, lane = tid & 31;
    const int g = lane >> 2, tig = lane & 3;
    const int wm = wid & 1;        // 0..1 : 32-row band
    const int wn = wid >> 1;       // 0..5 : 32-col band
    const int row0 = blockIdx.x * 64;
    const float* Wm[3] = {Wq, Wk, Wv};

    float acc[2][4][4];
#pragma unroll
    for (int mt = 0; mt < 2; mt++)
#pragma unroll
        for (int nt = 0; nt < 4; nt++)
#pragma unroll
            for (int i = 0; i < 4; i++) acc[mt][nt][i] = 0.f;

    for (int ch = 0; ch < C_ / 32; ch++) {
        const int k0 = ch * 32;
        __syncthreads();
        // X tile: 64 rows x 32 k = 512 float4.
        for (int i = tid; i < 512; i += 384) {
            int m = i >> 3, f4 = i & 7;
            float4 v = *reinterpret_cast<const float4*>(
                x + (size_t)(row0 + m) * C_ + k0 + f4 * 4);
            uint32_t h0, l0, h1, l1;
            split_pair(v.x, v.y, h0, l0);
            split_pair(v.z, v.w, h1, l1);
            int k = f4 * 4;
            *reinterpret_cast<uint32_t*>(&Xh[m][k])     = h0;
            *reinterpret_cast<uint32_t*>(&Xh[m][k + 2]) = h1;
            *reinterpret_cast<uint32_t*>(&Xl[m][k])     = l0;
            *reinterpret_cast<uint32_t*>(&Xl[m][k + 2]) = l1;
        }
        // W tiles: 32 k x 192 n = 1536 float4, transposed to [n][k].
        for (int i = tid; i < 1536; i += 384) {
            int k = i / 48, j = i % 48;
            int mat = j >> 4, f4 = j & 15;
            float4 v = *reinterpret_cast<const float4*>(
                Wm[mat] + (size_t)(k0 + k) * H_ + f4 * 4);
            int n0 = mat * 64 + f4 * 4;
            float f[4] = {v.x, v.y, v.z, v.w};
#pragma unroll
            for (int jj = 0; jj < 4; jj++) {
                __nv_bfloat16 h = __float2bfloat16(f[jj]);
                Wh[n0 + jj][k] = h;
                Wl[n0 + jj][k] = __float2bfloat16(f[jj] - __bfloat162float(h));
            }
        }
        __syncthreads();

#pragma unroll
        for (int ks = 0; ks < 2; ks++) {
            uint32_t ah[2][4], al[2][4];
#pragma unroll
            for (int mt = 0; mt < 2; mt++) {
                int rm = wm * 32 + mt * 16;
                int c0 = ks * 16 + 2 * tig;
                ah[mt][0] = *reinterpret_cast<const uint32_t*>(&Xh[rm + g][c0]);
                ah[mt][1] = *reinterpret_cast<const uint32_t*>(&Xh[rm + g + 8][c0]);
                ah[mt][2] = *reinterpret_cast<const uint32_t*>(&Xh[rm + g][c0 + 8]);
                ah[mt][3] = *reinterpret_cast<const uint32_t*>(&Xh[rm + g + 8][c0 + 8]);
                al[mt][0] = *reinterpret_cast<const uint32_t*>(&Xl[rm + g][c0]);
                al[mt][1] = *reinterpret_cast<const uint32_t*>(&Xl[rm + g + 8][c0]);
                al[mt][2] = *reinterpret_cast<const uint32_t*>(&Xl[rm + g][c0 + 8]);
                al[mt][3] = *reinterpret_cast<const uint32_t*>(&Xl[rm + g + 8][c0 + 8]);
            }
#pragma unroll
            for (int nt = 0; nt < 4; nt++) {
                int nb = wn * 32 + nt * 8;
                int c0 = ks * 16 + 2 * tig;
                uint32_t bh[2], bl[2];
                bh[0] = *reinterpret_cast<const uint32_t*>(&Wh[nb + g][c0]);
                bh[1] = *reinterpret_cast<const uint32_t*>(&Wh[nb + g][c0 + 8]);
                bl[0] = *reinterpret_cast<const uint32_t*>(&Wl[nb + g][c0]);
                bl[1] = *reinterpret_cast<const uint32_t*>(&Wl[nb + g][c0 + 8]);
#pragma unroll
                for (int mt = 0; mt < 2; mt++) {
                    mma_bf16(acc[mt][nt], ah[mt], bh);
                    mma_bf16(acc[mt][nt], ah[mt], bl);
                    mma_bf16(acc[mt][nt], al[mt], bh);
                }
            }
        }
    }

    // Epilogue: split to bf16 hi/lo and store. mat = wn>>1 (32-col bands).
    const int mat = wn >> 1;
    __nv_bfloat16* outh = (mat == 0) ? g_qh : (mat == 1) ? g_kh : g_vh;
    __nv_bfloat16* outl = (mat == 0) ? g_ql : (mat == 1) ? g_kl : g_vl;
    const float s = (mat == 0) ? 0.125f : 1.0f;   // 64^-0.5 folded into q
#pragma unroll
    for (int mt = 0; mt < 2; mt++)
#pragma unroll
        for (int nt = 0; nt < 4; nt++) {
            int r0 = row0 + wm * 32 + mt * 16 + g;
            int h = (wn * 32 + nt * 8 + 2 * tig) & 63;
            uint32_t hi, lo;
            split_pair(acc[mt][nt][0] * s, acc[mt][nt][1] * s, hi, lo);
            *reinterpret_cast<uint32_t*>(outh + (size_t)r0 * H_ + h) = hi;
            *reinterpret_cast<uint32_t*>(outl + (size_t)r0 * H_ + h) = lo;
            split_pair(acc[mt][nt][2] * s, acc[mt][nt][3] * s, hi, lo);
            *reinterpret_cast<uint32_t*>(outh + (size_t)(r0 + 8) * H_ + h) = hi;
            *reinterpret_cast<uint32_t*>(outl + (size_t)(r0 + 8) * H_ + h) = lo;
        }
}

// ===========================================================================
// Kernel 2: causal flash attention (tensor core).
// 256 threads = 8 warps; BM=128 queries (warp w owns rows w*16..w*16+15),
// KV tiles of 64. Q frags preloaded to registers. S and O accum in registers,
// online softmax per row pair, P frags built in-register (hi/lo split).
// ===========================================================================
#define KSTR 72   // smem key/h stride -> conflict-free LDS + ldmatrix

__global__ __launch_bounds__(256) void attn_kernel(float* __restrict__ out)
{
    __shared__ __nv_bfloat16 Ksh[64][KSTR], Ksl[64][KSTR];
    __shared__ __nv_bfloat16 Vsh[64][KSTR], Vsl[64][KSTR];

    const int b = blockIdx.y;
    const int qt0 = (int)(gridDim.x - 1 - blockIdx.x) * 128;  // longest first
    const int tid = threadIdx.x;
    const int wid = tid >> 5, lane = tid & 31;
    const int g = lane >> 2, tig = lane & 3;
    const int row_base = qt0 + wid * 16;
    const int row_max = row_base + 15;

    const __nv_bfloat16* qhp = g_qh + (size_t)b * T_ * H_;
    const __nv_bfloat16* qlp = g_ql + (size_t)b * T_ * H_;
    const __nv_bfloat16* khp = g_kh + (size_t)b * T_ * H_;
    const __nv_bfloat16* klp = g_kl + (size_t)b * T_ * H_;
    const __nv_bfloat16* vhp = g_vh + (size_t)b * T_ * H_;
    const __nv_bfloat16* vlp = g_vl + (size_t)b * T_ * H_;

    // Preload Q fragments (4 k16-slices x 4 regs, hi + lo).
    uint32_t qh[4][4], ql[4][4];
#pragma unroll
    for (int ks = 0; ks < 4; ks++) {
        int c0 = ks * 16 + 2 * tig;
        size_t r0 = (size_t)(row_base + g) * H_;
        size_t r1 = (size_t)(row_base + g + 8) * H_;
        qh[ks][0] = *reinterpret_cast<const uint32_t*>(qhp + r0 + c0);
        qh[ks][1] = *reinterpret_cast<const uint32_t*>(qhp + r1 + c0);
        qh[ks][2] = *reinterpret_cast<const uint32_t*>(qhp + r0 + c0 + 8);
        qh[ks][3] = *reinterpret_cast<const uint32_t*>(qhp + r1 + c0 + 8);
        ql[ks][0] = *reinterpret_cast<const uint32_t*>(qlp + r0 + c0);
        ql[ks][1] = *reinterpret_cast<const uint32_t*>(qlp + r1 + c0);
        ql[ks][2] = *reinterpret_cast<const uint32_t*>(qlp + r0 + c0 + 8);
        ql[ks][3] = *reinterpret_cast<const uint32_t*>(qlp + r1 + c0 + 8);
    }

    float oacc[8][4];
#pragma unroll
    for (int nt = 0; nt < 8; nt++)
#pragma unroll
        for (int i = 0; i < 4; i++) oacc[nt][i] = 0.f;
    float m0 = -1e30f, m1 = -1e30f, l0 = 0.f, l1 = 0.f;

    const uint32_t vsh0 = smem_u32(&Vsh[0][0]);
    const uint32_t vsl0 = smem_u32(&Vsl[0][0]);
    const int lm15 = lane & 15;    // ldmatrix row select

    const int ntiles = qt0 / 64 + 2;
    for (int it = 0; it < ntiles; it++) {
        const int s0 = it * 64;
        __syncthreads();
        // Load K/V tiles (hi/lo): 2048 u32 per array, 8 per thread, coalesced.
#pragma unroll
        for (int i = 0; i < 8; i++) {
            int idx = tid + i * 256;
            int r = idx >> 5, c = (idx & 31) * 2;
            size_t go = (size_t)(s0 + r) * H_ + c;
            *reinterpret_cast<uint32_t*>(&Ksh[r][c]) =
                *reinterpret_cast<const uint32_t*>(khp + go);
            *reinterpret_cast<uint32_t*>(&Ksl[r][c]) =
                *reinterpret_cast<const uint32_t*>(klp + go);
            *reinterpret_cast<uint32_t*>(&Vsh[r][c]) =
                *reinterpret_cast<const uint32_t*>(vhp + go);
            *reinterpret_cast<uint32_t*>(&Vsl[r][c]) =
                *reinterpret_cast<const uint32_t*>(vlp + go);
        }
        __syncthreads();
        if (s0 > row_max) continue;   // this warp's rows all precede the tile

        // ---- S = Q K^T ----
        float sacc[8][4];
#pragma unroll
        for (int nt = 0; nt < 8; nt++) {
            sacc[nt][0] = 0.f; sacc[nt][1] = 0.f;
            sacc[nt][2] = 0.f; sacc[nt][3] = 0.f;
#pragma unroll
            for (int ks = 0; ks < 4; ks++) {
                int c0 = ks * 16 + 2 * tig;
                uint32_t bh[2], bl[2];
                bh[0] = *reinterpret_cast<const uint32_t*>(&Ksh[nt * 8 + g][c0]);
                bh[1] = *reinterpret_cast<const uint32_t*>(&Ksh[nt * 8 + g][c0 + 8]);
                bl[0] = *reinterpret_cast<const uint32_t*>(&Ksl[nt * 8 + g][c0]);
                bl[1] = *reinterpret_cast<const uint32_t*>(&Ksl[nt * 8 + g][c0 + 8]);
                mma_bf16(sacc[nt], qh[ks], bh);
                mma_bf16(sacc[nt], qh[ks], bl);
                mma_bf16(sacc[nt], ql[ks], bh);
            }
        }

        // ---- causal mask (only on tiles crossing the diagonal) ----
        if (s0 + 63 > row_base) {
            const int r0 = row_base + g, r1 = r0 + 8;
#pragma unroll
            for (int nt = 0; nt < 8; nt++) {
                int c = s0 + nt * 8 + 2 * tig;
                if (c > r0)     sacc[nt][0] = -1e30f;
                if (c + 1 > r0) sacc[nt][1] = -1e30f;
                if (c > r1)     sacc[nt][2] = -1e30f;
                if (c + 1 > r1) sacc[nt][3] = -1e30f;
            }
        }

        // ---- online softmax (rows g and g+8 of this warp's m16 band) ----
        float rm0 = -1e30f, rm1 = -1e30f;
#pragma unroll
        for (int nt = 0; nt < 8; nt++) {
            rm0 = fmaxf(rm0, fmaxf(sacc[nt][0], sacc[nt][1]));
            rm1 = fmaxf(rm1, fmaxf(sacc[nt][2], sacc[nt][3]));
        }
        rm0 = fmaxf(rm0, __shfl_xor_sync(0xffffffffu, rm0, 1));
        rm0 = fmaxf(rm0, __shfl_xor_sync(0xffffffffu, rm0, 2));
        rm1 = fmaxf(rm1, __shfl_xor_sync(0xffffffffu, rm1, 1));
        rm1 = fmaxf(rm1, __shfl_xor_sync(0xffffffffu, rm1, 2));
        const float nm0 = fmaxf(m0, rm0), nm1 = fmaxf(m1, rm1);
        const float a0 = __expf(m0 - nm0), a1 = __expf(m1 - nm1);
        m0 = nm0; m1 = nm1;

        float ps0 = 0.f, ps1 = 0.f;
#pragma unroll
        for (int nt = 0; nt < 8; nt++) {
            sacc[nt][0] = __expf(sacc[nt][0] - nm0);
            sacc[nt][1] = __expf(sacc[nt][1] - nm0);
            sacc[nt][2] = __expf(sacc[nt][2] - nm1);
            sacc[nt][3] = __expf(sacc[nt][3] - nm1);
            ps0 += sacc[nt][0] + sacc[nt][1];
            ps1 += sacc[nt][2] + sacc[nt][3];
        }
        ps0 += __shfl_xor_sync(0xffffffffu, ps0, 1);
        ps0 += __shfl_xor_sync(0xffffffffu, ps0, 2);
        ps1 += __shfl_xor_sync(0xffffffffu, ps1, 1);
        ps1 += __shfl_xor_sync(0xffffffffu, ps1, 2);
        l0 = l0 * a0 + ps0;
        l1 = l1 * a1 + ps1;
#pragma unroll
        for (int nt = 0; nt < 8; nt++) {
            oacc[nt][0] *= a0; oacc[nt][1] *= a0;
            oacc[nt][2] *= a1; oacc[nt][3] *= a1;
        }

        // ---- O += P V : P frags in-register (D->A layout identity) ----
#pragma unroll
        for (int ks = 0; ks < 4; ks++) {
            uint32_t ph[4], pl[4];
            split_pair(sacc[2 * ks][0],     sacc[2 * ks][1],     ph[0], pl[0]);
            split_pair(sacc[2 * ks][2],     sacc[2 * ks][3],     ph[1], pl[1]);
            split_pair(sacc[2 * ks + 1][0], sacc[2 * ks + 1][1], ph[2], pl[2]);
            split_pair(sacc[2 * ks + 1][2], sacc[2 * ks + 1][3], ph[3], pl[3]);
            const uint32_t rowoff = (uint32_t)((ks * 16 + lm15) * KSTR) * 2u;
#pragma unroll
            for (int nt = 0; nt < 8; nt++) {
                uint32_t bh[2], bl[2];
                ldsm_x2_trans(bh[0], bh[1], vsh0 + rowoff + (uint32_t)(nt * 16));
                ldsm_x2_trans(bl[0], bl[1], vsl0 + rowoff + (uint32_t)(nt * 16));
                mma_bf16(oacc[nt], ph, bh);
                mma_bf16(oacc[nt], ph, bl);
                mma_bf16(oacc[nt], pl, bh);
            }
        }
    }

    // ---- epilogue ----
    const float inv0 = 1.f / l0, inv1 = 1.f / l1;
    float* orow0 = out + ((size_t)b * T_ + row_base + g) * H_;
    float* orow1 = out + ((size_t)b * T_ + row_base + g + 8) * H_;
#pragma unroll
    for (int nt = 0; nt < 8; nt++) {
        int c = nt * 8 + 2 * tig;
        float2 v0 = make_float2(oacc[nt][0] * inv0, oacc[nt][1] * inv0);
        float2 v1 = make_float2(oacc[nt][2] * inv1, oacc[nt][3] * inv1);
        *reinterpret_cast<float2*>(orow0 + c) = v0;
        *reinterpret_cast<float2*>(orow1 + c) = v1;
    }
}

// ===========================================================================
extern "C" void kernel_launch(void* const* d_in, const int* in_sizes, int n_in,
                              void* d_out, int out_size)
{
    const float* x  = (const float*)d_in[0];
    const float* Wq = (const float*)d_in[1];
    const float* Wk = (const float*)d_in[2];
    const float* Wv = (const float*)d_in[3];
    float* out = (float*)d_out;

    proj_kernel<<<(B_ * T_) / 64, 384>>>(x, Wq, Wk, Wv);

    dim3 gattn(T_ / 128, B_);
    attn_kernel<<<gattn, 256>>>(out);
}

// round 5
// speedup vs baseline: 3.1361x; 1.8153x over previous
#include <cuda_runtime.h>
#include <cuda_bf16.h>
#include <cstdint>

#define B_  16
#define T_  2048
#define C_  1024
#define H_  64

// q/k/v stored pre-split as bf16 hi/lo pairs.
__device__ __nv_bfloat16 g_qh[(size_t)B_ * T_ * H_];
__device__ __nv_bfloat16 g_ql[(size_t)B_ * T_ * H_];
__device__ __nv_bfloat16 g_kh[(size_t)B_ * T_ * H_];
__device__ __nv_bfloat16 g_kl[(size_t)B_ * T_ * H_];
__device__ __nv_bfloat16 g_vh[(size_t)B_ * T_ * H_];
__device__ __nv_bfloat16 g_vl[(size_t)B_ * T_ * H_];

// W pre-split + transposed: row n = mat*64 + h (0..191), col k (0..1023).
__device__ __nv_bfloat16 g_wh[192 * C_];
__device__ __nv_bfloat16 g_wl[192 * C_];

// ---------------------------------------------------------------------------
__device__ __forceinline__ void mma_bf16(float* d, const uint32_t* a,
                                         const uint32_t* b) {
    asm volatile(
        "mma.sync.aligned.m16n8k16.row.col.f32.bf16.bf16.f32 "
        "{%0,%1,%2,%3}, {%4,%5,%6,%7}, {%8,%9}, {%0,%1,%2,%3};"
        : "+f"(d[0]), "+f"(d[1]), "+f"(d[2]), "+f"(d[3])
        : "r"(a[0]), "r"(a[1]), "r"(a[2]), "r"(a[3]), "r"(b[0]), "r"(b[1]));
}

__device__ __forceinline__ void ldsm_x2_trans(uint32_t& r0, uint32_t& r1,
                                              uint32_t addr) {
    asm volatile("ldmatrix.sync.aligned.m8n8.x2.trans.shared.b16 {%0,%1}, [%2];"
                 : "=r"(r0), "=r"(r1) : "r"(addr));
}

__device__ __forceinline__ uint32_t smem_u32(const void* p) {
    uint32_t a;
    asm("{ .reg .u64 t; cvta.to.shared.u64 t, %1; cvt.u32.u64 %0, t; }"
        : "=r"(a) : "l"(p));
    return a;
}

__device__ __forceinline__ void split_pair(float x, float y,
                                           uint32_t& hi, uint32_t& lo) {
    __nv_bfloat16 hx = __float2bfloat16(x);
    __nv_bfloat16 hy = __float2bfloat16(y);
    __nv_bfloat162 hv(hx, hy);
    hi = *reinterpret_cast<uint32_t*>(&hv);
    __nv_bfloat162 lv = __floats2bfloat162_rn(x - __bfloat162float(hx),
                                              y - __bfloat162float(hy));
    lo = *reinterpret_cast<uint32_t*>(&lv);
}

// ===========================================================================
// Kernel 0: one-time W split/transpose. 192 blocks x 256 threads.
// Row n = mat*64 + h, value = W_mat[k][h] (* 0.125 for q).
// ===========================================================================
__global__ __launch_bounds__(256) void split_w_kernel(
    const float* __restrict__ Wq,
    const float* __restrict__ Wk,
    const float* __restrict__ Wv)
{
    const int n = blockIdx.x;             // 0..191
    const int mat = n >> 6;
    const int h = n & 63;
    const float* W = (mat == 0) ? Wq : (mat == 1) ? Wk : Wv;
    const float s = (mat == 0) ? 0.125f : 1.0f;

    for (int k = threadIdx.x; k < C_; k += 256) {
        float v = W[(size_t)k * H_ + h] * s;
        __nv_bfloat16 hb = __float2bfloat16(v);
        g_wh[(size_t)n * C_ + k] = hb;
        g_wl[(size_t)n * C_ + k] = __float2bfloat16(v - __bfloat162float(hb));
    }
}

// ===========================================================================
// Kernel 1: QKV projection (tensor core), pre-split W.
// C[64 rows][192 cols] per block. BK=32, 384 threads: 2 m-warps x 6 n-warps.
// ===========================================================================
#define PSTR 40   // smem k-stride: 80B rows -> 16B-aligned, conflict-free

__global__ __launch_bounds__(384) void proj_kernel(const float* __restrict__ x)
{
    __shared__ __nv_bfloat16 Xh[64][PSTR],  Xl[64][PSTR];
    __shared__ __nv_bfloat16 Wh[192][PSTR], Wl[192][PSTR];

    const int tid = threadIdx.x;
    const int wid = tid >> 5, lane = tid & 31;
    const int g = lane >> 2, tig = lane & 3;
    const int wm = wid & 1;        // 0..1 : 32-row band
    const int wn = wid >> 1;       // 0..5 : 32-col band
    const int row0 = blockIdx.x * 64;

    float acc[2][4][4];
#pragma unroll
    for (int mt = 0; mt < 2; mt++)
#pragma unroll
        for (int nt = 0; nt < 4; nt++)
#pragma unroll
            for (int i = 0; i < 4; i++) acc[mt][nt][i] = 0.f;

    for (int ch = 0; ch < C_ / 32; ch++) {
        const int k0 = ch * 32;
        __syncthreads();
        // X tile: 64 rows x 32 k = 512 float4 reads, split to bf16 hi/lo.
        for (int i = tid; i < 512; i += 384) {
            int m = i >> 3, f4 = i & 7;
            float4 v = *reinterpret_cast<const float4*>(
                x + (size_t)(row0 + m) * C_ + k0 + f4 * 4);
            uint32_t h0, l0, h1, l1;
            split_pair(v.x, v.y, h0, l0);
            split_pair(v.z, v.w, h1, l1);
            int k = f4 * 4;
            *reinterpret_cast<uint32_t*>(&Xh[m][k])     = h0;
            *reinterpret_cast<uint32_t*>(&Xh[m][k + 2]) = h1;
            *reinterpret_cast<uint32_t*>(&Xl[m][k])     = l0;
            *reinterpret_cast<uint32_t*>(&Xl[m][k + 2]) = l1;
        }
        // W tiles: 192 rows x 32 k = 768 uint4 per array, pure copies.
        for (int i = tid; i < 768; i += 384) {
            int n = i >> 2, q = i & 3;
            *reinterpret_cast<uint4*>(&Wh[n][q * 8]) =
                *reinterpret_cast<const uint4*>(g_wh + (size_t)n * C_ + k0 + q * 8);
            *reinterpret_cast<uint4*>(&Wl[n][q * 8]) =
                *reinterpret_cast<const uint4*>(g_wl + (size_t)n * C_ + k0 + q * 8);
        }
        __syncthreads();

#pragma unroll
        for (int ks = 0; ks < 2; ks++) {
            uint32_t ah[2][4], al[2][4];
#pragma unroll
            for (int mt = 0; mt < 2; mt++) {
                int rm = wm * 32 + mt * 16;
                int c0 = ks * 16 + 2 * tig;
                ah[mt][0] = *reinterpret_cast<const uint32_t*>(&Xh[rm + g][c0]);
                ah[mt][1] = *reinterpret_cast<const uint32_t*>(&Xh[rm + g + 8][c0]);
                ah[mt][2] = *reinterpret_cast<const uint32_t*>(&Xh[rm + g][c0 + 8]);
                ah[mt][3] = *reinterpret_cast<const uint32_t*>(&Xh[rm + g + 8][c0 + 8]);
                al[mt][0] = *reinterpret_cast<const uint32_t*>(&Xl[rm + g][c0]);
                al[mt][1] = *reinterpret_cast<const uint32_t*>(&Xl[rm + g + 8][c0]);
                al[mt][2] = *reinterpret_cast<const uint32_t*>(&Xl[rm + g][c0 + 8]);
                al[mt][3] = *reinterpret_cast<const uint32_t*>(&Xl[rm + g + 8][c0 + 8]);
            }
#pragma unroll
            for (int nt = 0; nt < 4; nt++) {
                int nb = wn * 32 + nt * 8;
                int c0 = ks * 16 + 2 * tig;
                uint32_t bh[2], bl[2];
                bh[0] = *reinterpret_cast<const uint32_t*>(&Wh[nb + g][c0]);
                bh[1] = *reinterpret_cast<const uint32_t*>(&Wh[nb + g][c0 + 8]);
                bl[0] = *reinterpret_cast<const uint32_t*>(&Wl[nb + g][c0]);
                bl[1] = *reinterpret_cast<const uint32_t*>(&Wl[nb + g][c0 + 8]);
#pragma unroll
                for (int mt = 0; mt < 2; mt++) {
                    mma_bf16(acc[mt][nt], ah[mt], bh);
                    mma_bf16(acc[mt][nt], ah[mt], bl);
                    mma_bf16(acc[mt][nt], al[mt], bh);
                }
            }
        }
    }

    // Epilogue: split to bf16 hi/lo and store (q scale already in W).
    const int mat = wn >> 1;
    __nv_bfloat16* outh = (mat == 0) ? g_qh : (mat == 1) ? g_kh : g_vh;
    __nv_bfloat16* outl = (mat == 0) ? g_ql : (mat == 1) ? g_kl : g_vl;
#pragma unroll
    for (int mt = 0; mt < 2; mt++)
#pragma unroll
        for (int nt = 0; nt < 4; nt++) {
            int r0 = row0 + wm * 32 + mt * 16 + g;
            int h = (wn * 32 + nt * 8 + 2 * tig) & 63;
            uint32_t hi, lo;
            split_pair(acc[mt][nt][0], acc[mt][nt][1], hi, lo);
            *reinterpret_cast<uint32_t*>(outh + (size_t)r0 * H_ + h) = hi;
            *reinterpret_cast<uint32_t*>(outl + (size_t)r0 * H_ + h) = lo;
            split_pair(acc[mt][nt][2], acc[mt][nt][3], hi, lo);
            *reinterpret_cast<uint32_t*>(outh + (size_t)(r0 + 8) * H_ + h) = hi;
            *reinterpret_cast<uint32_t*>(outl + (size_t)(r0 + 8) * H_ + h) = lo;
        }
}

// ===========================================================================
// Kernel 2: causal flash attention (tensor core) — unchanged from R4.
// ===========================================================================
#define KSTR 72

__global__ __launch_bounds__(256) void attn_kernel(float* __restrict__ out)
{
    __shared__ __nv_bfloat16 Ksh[64][KSTR], Ksl[64][KSTR];
    __shared__ __nv_bfloat16 Vsh[64][KSTR], Vsl[64][KSTR];

    const int b = blockIdx.y;
    const int qt0 = (int)(gridDim.x - 1 - blockIdx.x) * 128;
    const int tid = threadIdx.x;
    const int wid = tid >> 5, lane = tid & 31;
    const int g = lane >> 2, tig = lane & 3;
    const int row_base = qt0 + wid * 16;
    const int row_max = row_base + 15;

    const __nv_bfloat16* qhp = g_qh + (size_t)b * T_ * H_;
    const __nv_bfloat16* qlp = g_ql + (size_t)b * T_ * H_;
    const __nv_bfloat16* khp = g_kh + (size_t)b * T_ * H_;
    const __nv_bfloat16* klp = g_kl + (size_t)b * T_ * H_;
    const __nv_bfloat16* vhp = g_vh + (size_t)b * T_ * H_;
    const __nv_bfloat16* vlp = g_vl + (size_t)b * T_ * H_;

    uint32_t qh[4][4], ql[4][4];
#pragma unroll
    for (int ks = 0; ks < 4; ks++) {
        int c0 = ks * 16 + 2 * tig;
        size_t r0 = (size_t)(row_base + g) * H_;
        size_t r1 = (size_t)(row_base + g + 8) * H_;
        qh[ks][0] = *reinterpret_cast<const uint32_t*>(qhp + r0 + c0);
        qh[ks][1] = *reinterpret_cast<const uint32_t*>(qhp + r1 + c0);
        qh[ks][2] = *reinterpret_cast<const uint32_t*>(qhp + r0 + c0 + 8);
        qh[ks][3] = *reinterpret_cast<const uint32_t*>(qhp + r1 + c0 + 8);
        ql[ks][0] = *reinterpret_cast<const uint32_t*>(qlp + r0 + c0);
        ql[ks][1] = *reinterpret_cast<const uint32_t*>(qlp + r1 + c0);
        ql[ks][2] = *reinterpret_cast<const uint32_t*>(qlp + r0 + c0 + 8);
        ql[ks][3] = *reinterpret_cast<const uint32_t*>(qlp + r1 + c0 + 8);
    }

    float oacc[8][4];
#pragma unroll
    for (int nt = 0; nt < 8; nt++)
#pragma unroll
        for (int i = 0; i < 4; i++) oacc[nt][i] = 0.f;
    float m0 = -1e30f, m1 = -1e30f, l0 = 0.f, l1 = 0.f;

    const uint32_t vsh0 = smem_u32(&Vsh[0][0]);
    const uint32_t vsl0 = smem_u32(&Vsl[0][0]);
    const int lm15 = lane & 15;

    const int ntiles = qt0 / 64 + 2;
    for (int it = 0; it < ntiles; it++) {
        const int s0 = it * 64;
        __syncthreads();
#pragma unroll
        for (int i = 0; i < 8; i++) {
            int idx = tid + i * 256;
            int r = idx >> 5, c = (idx & 31) * 2;
            size_t go = (size_t)(s0 + r) * H_ + c;
            *reinterpret_cast<uint32_t*>(&Ksh[r][c]) =
                *reinterpret_cast<const uint32_t*>(khp + go);
            *reinterpret_cast<uint32_t*>(&Ksl[r][c]) =
                *reinterpret_cast<const uint32_t*>(klp + go);
            *reinterpret_cast<uint32_t*>(&Vsh[r][c]) =
                *reinterpret_cast<const uint32_t*>(vhp + go);
            *reinterpret_cast<uint32_t*>(&Vsl[r][c]) =
                *reinterpret_cast<const uint32_t*>(vlp + go);
        }
        __syncthreads();
        if (s0 > row_max) continue;

        float sacc[8][4];
#pragma unroll
        for (int nt = 0; nt < 8; nt++) {
            sacc[nt][0] = 0.f; sacc[nt][1] = 0.f;
            sacc[nt][2] = 0.f; sacc[nt][3] = 0.f;
#pragma unroll
            for (int ks = 0; ks < 4; ks++) {
                int c0 = ks * 16 + 2 * tig;
                uint32_t bh[2], bl[2];
                bh[0] = *reinterpret_cast<const uint32_t*>(&Ksh[nt * 8 + g][c0]);
                bh[1] = *reinterpret_cast<const uint32_t*>(&Ksh[nt * 8 + g][c0 + 8]);
                bl[0] = *reinterpret_cast<const uint32_t*>(&Ksl[nt * 8 + g][c0]);
                bl[1] = *reinterpret_cast<const uint32_t*>(&Ksl[nt * 8 + g][c0 + 8]);
                mma_bf16(sacc[nt], qh[ks], bh);
                mma_bf16(sacc[nt], qh[ks], bl);
                mma_bf16(sacc[nt], ql[ks], bh);
            }
        }

        if (s0 + 63 > row_base) {
            const int r0 = row_base + g, r1 = r0 + 8;
#pragma unroll
            for (int nt = 0; nt < 8; nt++) {
                int c = s0 + nt * 8 + 2 * tig;
                if (c > r0)     sacc[nt][0] = -1e30f;
                if (c + 1 > r0) sacc[nt][1] = -1e30f;
                if (c > r1)     sacc[nt][2] = -1e30f;
                if (c + 1 > r1) sacc[nt][3] = -1e30f;
            }
        }

        float rm0 = -1e30f, rm1 = -1e30f;
#pragma unroll
        for (int nt = 0; nt < 8; nt++) {
            rm0 = fmaxf(rm0, fmaxf(sacc[nt][0], sacc[nt][1]));
            rm1 = fmaxf(rm1, fmaxf(sacc[nt][2], sacc[nt][3]));
        }
        rm0 = fmaxf(rm0, __shfl_xor_sync(0xffffffffu, rm0, 1));
        rm0 = fmaxf(rm0, __shfl_xor_sync(0xffffffffu, rm0, 2));
        rm1 = fmaxf(rm1, __shfl_xor_sync(0xffffffffu, rm1, 1));
        rm1 = fmaxf(rm1, __shfl_xor_sync(0xffffffffu, rm1, 2));
        const float nm0 = fmaxf(m0, rm0), nm1 = fmaxf(m1, rm1);
        const float a0 = __expf(m0 - nm0), a1 = __expf(m1 - nm1);
        m0 = nm0; m1 = nm1;

        float ps0 = 0.f, ps1 = 0.f;
#pragma unroll
        for (int nt = 0; nt < 8; nt++) {
            sacc[nt][0] = __expf(sacc[nt][0] - nm0);
            sacc[nt][1] = __expf(sacc[nt][1] - nm0);
            sacc[nt][2] = __expf(sacc[nt][2] - nm1);
            sacc[nt][3] = __expf(sacc[nt][3] - nm1);
            ps0 += sacc[nt][0] + sacc[nt][1];
            ps1 += sacc[nt][2] + sacc[nt][3];
        }
        ps0 += __shfl_xor_sync(0xffffffffu, ps0, 1);
        ps0 += __shfl_xor_sync(0xffffffffu, ps0, 2);
        ps1 += __shfl_xor_sync(0xffffffffu, ps1, 1);
        ps1 += __shfl_xor_sync(0xffffffffu, ps1, 2);
        l0 = l0 * a0 + ps0;
        l1 = l1 * a1 + ps1;
#pragma unroll
        for (int nt = 0; nt < 8; nt++) {
            oacc[nt][0] *= a0; oacc[nt][1] *= a0;
            oacc[nt][2] *= a1; oacc[nt][3] *= a1;
        }

#pragma unroll
        for (int ks = 0; ks < 4; ks++) {
            uint32_t ph[4], pl[4];
            split_pair(sacc[2 * ks][0],     sacc[2 * ks][1],     ph[0], pl[0]);
            split_pair(sacc[2 * ks][2],     sacc[2 * ks][3],     ph[1], pl[1]);
            split_pair(sacc[2 * ks + 1][0], sacc[2 * ks + 1][1], ph[2], pl[2]);
            split_pair(sacc[2 * ks + 1][2], sacc[2 * ks + 1][3], ph[3], pl[3]);
            const uint32_t rowoff = (uint32_t)((ks * 16 + lm15) * KSTR) * 2u;
#pragma unroll
            for (int nt = 0; nt < 8; nt++) {
                uint32_t bh[2], bl[2];
                ldsm_x2_trans(bh[0], bh[1], vsh0 + rowoff + (uint32_t)(nt * 16));
                ldsm_x2_trans(bl[0], bl[1], vsl0 + rowoff + (uint32_t)(nt * 16));
                mma_bf16(oacc[nt], ph, bh);
                mma_bf16(oacc[nt], ph, bl);
                mma_bf16(oacc[nt], pl, bh);
            }
        }
    }

    const float inv0 = 1.f / l0, inv1 = 1.f / l1;
    float* orow0 = out + ((size_t)b * T_ + row_base + g) * H_;
    float* orow1 = out + ((size_t)b * T_ + row_base + g + 8) * H_;
#pragma unroll
    for (int nt = 0; nt < 8; nt++) {
        int c = nt * 8 + 2 * tig;
        float2 v0 = make_float2(oacc[nt][0] * inv0, oacc[nt][1] * inv0);
        float2 v1 = make_float2(oacc[nt][2] * inv1, oacc[nt][3] * inv1);
        *reinterpret_cast<float2*>(orow0 + c) = v0;
        *reinterpret_cast<float2*>(orow1 + c) = v1;
    }
}

// ===========================================================================
extern "C" void kernel_launch(void* const* d_in, const int* in_sizes, int n_in,
                              void* d_out, int out_size)
{
    const float* x  = (const float*)d_in[0];
    const float* Wq = (const float*)d_in[1];
    const float* Wk = (const float*)d_in[2];
    const float* Wv = (const float*)d_in[3];
    float* out = (float*)d_out;

    split_w_kernel<<<192, 256>>>(Wq, Wk, Wv);
    proj_kernel<<<(B_ * T_) / 64, 384>>>(x);

    dim3 gattn(T_ / 128, B_);
    attn_kernel<<<gattn, 256>>>(out);
}

// round 6
// speedup vs baseline: 3.2291x; 1.0296x over previous
#include <cuda_runtime.h>
#include <cuda_bf16.h>
#include <cstdint>

#define B_  16
#define T_  2048
#define C_  1024
#define H_  64

// q/k/v stored pre-split as bf16 hi/lo pairs.
__device__ __nv_bfloat16 g_qh[(size_t)B_ * T_ * H_];
__device__ __nv_bfloat16 g_ql[(size_t)B_ * T_ * H_];
__device__ __nv_bfloat16 g_kh[(size_t)B_ * T_ * H_];
__device__ __nv_bfloat16 g_kl[(size_t)B_ * T_ * H_];
__device__ __nv_bfloat16 g_vh[(size_t)B_ * T_ * H_];
__device__ __nv_bfloat16 g_vl[(size_t)B_ * T_ * H_];

// W pre-split + transposed: row n = mat*64 + h (0..191), col k (0..1023).
__device__ __nv_bfloat16 g_wh[192 * C_];
__device__ __nv_bfloat16 g_wl[192 * C_];

// ---------------------------------------------------------------------------
__device__ __forceinline__ void mma_bf16(float* d, const uint32_t* a,
                                         const uint32_t* b) {
    asm volatile(
        "mma.sync.aligned.m16n8k16.row.col.f32.bf16.bf16.f32 "
        "{%0,%1,%2,%3}, {%4,%5,%6,%7}, {%8,%9}, {%0,%1,%2,%3};"
        : "+f"(d[0]), "+f"(d[1]), "+f"(d[2]), "+f"(d[3])
        : "r"(a[0]), "r"(a[1]), "r"(a[2]), "r"(a[3]), "r"(b[0]), "r"(b[1]));
}

__device__ __forceinline__ void ldsm_x2_trans(uint32_t& r0, uint32_t& r1,
                                              uint32_t addr) {
    asm volatile("ldmatrix.sync.aligned.m8n8.x2.trans.shared.b16 {%0,%1}, [%2];"
                 : "=r"(r0), "=r"(r1) : "r"(addr));
}

__device__ __forceinline__ uint32_t smem_u32(const void* p) {
    uint32_t a;
    asm("{ .reg .u64 t; cvta.to.shared.u64 t, %1; cvt.u32.u64 %0, t; }"
        : "=r"(a) : "l"(p));
    return a;
}

#define CP_ASYNC16(dst, src) \
    asm volatile("cp.async.cg.shared.global [%0], [%1], 16;" \
                 :: "r"(dst), "l"(src) : "memory")
#define CP_COMMIT() asm volatile("cp.async.commit_group;" ::: "memory")
#define CP_WAIT0()  asm volatile("cp.async.wait_group 0;" ::: "memory")
#define CP_WAIT1()  asm volatile("cp.async.wait_group 1;" ::: "memory")

__device__ __forceinline__ void split_pair(float x, float y,
                                           uint32_t& hi, uint32_t& lo) {
    __nv_bfloat16 hx = __float2bfloat16(x);
    __nv_bfloat16 hy = __float2bfloat16(y);
    __nv_bfloat162 hv(hx, hy);
    hi = *reinterpret_cast<uint32_t*>(&hv);
    __nv_bfloat162 lv = __floats2bfloat162_rn(x - __bfloat162float(hx),
                                              y - __bfloat162float(hy));
    lo = *reinterpret_cast<uint32_t*>(&lv);
}

// ===========================================================================
// Kernel 0: one-time W split/transpose.
// ===========================================================================
__global__ __launch_bounds__(256) void split_w_kernel(
    const float* __restrict__ Wq,
    const float* __restrict__ Wk,
    const float* __restrict__ Wv)
{
    const int n = blockIdx.x;             // 0..191
    const int mat = n >> 6;
    const int h = n & 63;
    const float* W = (mat == 0) ? Wq : (mat == 1) ? Wk : Wv;
    const float s = (mat == 0) ? 0.125f : 1.0f;

    for (int k = threadIdx.x; k < C_; k += 256) {
        float v = W[(size_t)k * H_ + h] * s;
        __nv_bfloat16 hb = __float2bfloat16(v);
        g_wh[(size_t)n * C_ + k] = hb;
        g_wl[(size_t)n * C_ + k] = __float2bfloat16(v - __bfloat162float(hb));
    }
}

// ===========================================================================
// Kernel 1: QKV projection, cp.async double-buffered, 1 sync per K-chunk.
// C[64 rows][192 cols] per block, BK=32, 384 threads (2 m-warps x 6 n-warps).
// Dyn smem (bf16 elems): Xh[2][64][40] | Xl | Wh[2][192][40] | Wl  = 80 KB.
// ===========================================================================
#define PSTR 40
#define PX_STG (64 * PSTR)          // 2560 elems per X stage
#define PW_STG (192 * PSTR)         // 7680 elems per W stage
#define XH_OFF 0
#define XL_OFF (2 * PX_STG)         // 5120
#define WH_OFF (4 * PX_STG)         // 10240
#define WL_OFF (WH_OFF + 2 * PW_STG) // 25600
#define PROJ_SMEM ((WL_OFF + 2 * PW_STG) * 2)   // 81920 bytes

__global__ __launch_bounds__(384) void proj_kernel(const float* __restrict__ x)
{
    extern __shared__ __nv_bfloat16 SM[];
    const uint32_t smb = smem_u32(SM);

    const int tid = threadIdx.x;
    const int wid = tid >> 5, lane = tid & 31;
    const int g = lane >> 2, tig = lane & 3;
    const int wm = wid & 1;
    const int wn = wid >> 1;
    const int row0 = blockIdx.x * 64;

    float acc[2][4][4];
#pragma unroll
    for (int mt = 0; mt < 2; mt++)
#pragma unroll
        for (int nt = 0; nt < 4; nt++)
#pragma unroll
            for (int i = 0; i < 4; i++) acc[mt][nt][i] = 0.f;

    // x element mapping: idx = tid + j*384 (<512): m=idx>>3, f4=idx&7.
    const int xm0 = tid >> 3, xf0 = tid & 7;
    const int xi1 = tid + 384;
    const int xm1 = xi1 >> 3, xf1 = xi1 & 7;
    const bool x2 = (tid < 128);

    float4 xv0, xv1;

    // W cp.async issue: per array 768 uint4, thread does i = tid, tid+384.
    auto w_prefetch = [&](int k0, int stg) {
#pragma unroll
        for (int j = 0; j < 2; j++) {
            int i = tid + j * 384;
            int n = i >> 2, q = i & 3;
            uint32_t dh = smb + (uint32_t)(WH_OFF + stg * PW_STG + n * PSTR + q * 8) * 2;
            uint32_t dl = smb + (uint32_t)(WL_OFF + stg * PW_STG + n * PSTR + q * 8) * 2;
            CP_ASYNC16(dh, g_wh + (size_t)n * C_ + k0 + q * 8);
            CP_ASYNC16(dl, g_wl + (size_t)n * C_ + k0 + q * 8);
        }
    };
    auto x_load = [&](int k0) {
        xv0 = *reinterpret_cast<const float4*>(
            x + (size_t)(row0 + xm0) * C_ + k0 + xf0 * 4);
        if (x2)
            xv1 = *reinterpret_cast<const float4*>(
                x + (size_t)(row0 + xm1) * C_ + k0 + xf1 * 4);
    };
    auto x_store = [&](int stg) {
        __nv_bfloat16* Xh = SM + XH_OFF + stg * PX_STG;
        __nv_bfloat16* Xl = SM + XL_OFF + stg * PX_STG;
        uint32_t h0, l0, h1, l1;
        split_pair(xv0.x, xv0.y, h0, l0);
        split_pair(xv0.z, xv0.w, h1, l1);
        int o = xm0 * PSTR + xf0 * 4;
        *reinterpret_cast<uint32_t*>(Xh + o)     = h0;
        *reinterpret_cast<uint32_t*>(Xh + o + 2) = h1;
        *reinterpret_cast<uint32_t*>(Xl + o)     = l0;
        *reinterpret_cast<uint32_t*>(Xl + o + 2) = l1;
        if (x2) {
            split_pair(xv1.x, xv1.y, h0, l0);
            split_pair(xv1.z, xv1.w, h1, l1);
            o = xm1 * PSTR + xf1 * 4;
            *reinterpret_cast<uint32_t*>(Xh + o)     = h0;
            *reinterpret_cast<uint32_t*>(Xh + o + 2) = h1;
            *reinterpret_cast<uint32_t*>(Xl + o)     = l0;
            *reinterpret_cast<uint32_t*>(Xl + o + 2) = l1;
        }
    };

    // Prologue: chunk 0 into stage 0.
    x_load(0);
    w_prefetch(0, 0);
    CP_COMMIT();
    x_store(0);
    CP_WAIT0();
    __syncthreads();

    for (int ch = 0; ch < 32; ch++) {
        const int s = ch & 1;
        if (ch < 31) {
            x_load((ch + 1) * 32);
            w_prefetch((ch + 1) * 32, s ^ 1);
            CP_COMMIT();
        }

        // ---- compute on stage s ----
        const __nv_bfloat16* Xh = SM + XH_OFF + s * PX_STG;
        const __nv_bfloat16* Xl = SM + XL_OFF + s * PX_STG;
        const __nv_bfloat16* Wh = SM + WH_OFF + s * PW_STG;
        const __nv_bfloat16* Wl = SM + WL_OFF + s * PW_STG;
#pragma unroll
        for (int ks = 0; ks < 2; ks++) {
            const int c0 = ks * 16 + 2 * tig;
            uint32_t ah[2][4], al[2][4];
#pragma unroll
            for (int mt = 0; mt < 2; mt++) {
                int rm = wm * 32 + mt * 16;
                ah[mt][0] = *reinterpret_cast<const uint32_t*>(Xh + (rm + g) * PSTR + c0);
                ah[mt][1] = *reinterpret_cast<const uint32_t*>(Xh + (rm + g + 8) * PSTR + c0);
                ah[mt][2] = *reinterpret_cast<const uint32_t*>(Xh + (rm + g) * PSTR + c0 + 8);
                ah[mt][3] = *reinterpret_cast<const uint32_t*>(Xh + (rm + g + 8) * PSTR + c0 + 8);
                al[mt][0] = *reinterpret_cast<const uint32_t*>(Xl + (rm + g) * PSTR + c0);
                al[mt][1] = *reinterpret_cast<const uint32_t*>(Xl + (rm + g + 8) * PSTR + c0);
                al[mt][2] = *reinterpret_cast<const uint32_t*>(Xl + (rm + g) * PSTR + c0 + 8);
                al[mt][3] = *reinterpret_cast<const uint32_t*>(Xl + (rm + g + 8) * PSTR + c0 + 8);
            }
#pragma unroll
            for (int nt = 0; nt < 4; nt++) {
                int nb = wn * 32 + nt * 8;
                uint32_t bh[2], bl[2];
                bh[0] = *reinterpret_cast<const uint32_t*>(Wh + (nb + g) * PSTR + c0);
                bh[1] = *reinterpret_cast<const uint32_t*>(Wh + (nb + g) * PSTR + c0 + 8);
                bl[0] = *reinterpret_cast<const uint32_t*>(Wl + (nb + g) * PSTR + c0);
                bl[1] = *reinterpret_cast<const uint32_t*>(Wl + (nb + g) * PSTR + c0 + 8);
#pragma unroll
                for (int mt = 0; mt < 2; mt++) {
                    mma_bf16(acc[mt][nt], ah[mt], bh);
                    mma_bf16(acc[mt][nt], ah[mt], bl);
                    mma_bf16(acc[mt][nt], al[mt], bh);
                }
            }
        }

        if (ch < 31) {
            x_store(s ^ 1);
            CP_WAIT0();
        }
        __syncthreads();
    }

    // Epilogue: split to bf16 hi/lo, store (q scale already folded into W).
    const int mat = wn >> 1;
    __nv_bfloat16* outh = (mat == 0) ? g_qh : (mat == 1) ? g_kh : g_vh;
    __nv_bfloat16* outl = (mat == 0) ? g_ql : (mat == 1) ? g_kl : g_vl;
#pragma unroll
    for (int mt = 0; mt < 2; mt++)
#pragma unroll
        for (int nt = 0; nt < 4; nt++) {
            int r0 = row0 + wm * 32 + mt * 16 + g;
            int h = (wn * 32 + nt * 8 + 2 * tig) & 63;
            uint32_t hi, lo;
            split_pair(acc[mt][nt][0], acc[mt][nt][1], hi, lo);
            *reinterpret_cast<uint32_t*>(outh + (size_t)r0 * H_ + h) = hi;
            *reinterpret_cast<uint32_t*>(outl + (size_t)r0 * H_ + h) = lo;
            split_pair(acc[mt][nt][2], acc[mt][nt][3], hi, lo);
            *reinterpret_cast<uint32_t*>(outh + (size_t)(r0 + 8) * H_ + h) = hi;
            *reinterpret_cast<uint32_t*>(outl + (size_t)(r0 + 8) * H_ + h) = lo;
        }
}

// ===========================================================================
// Kernel 2: causal flash attention, BM=64 (4 warps / 128 thr), 512 blocks,
// cp.async double-buffered KV tiles (64 keys).
// Dyn smem: [2 stages][4 arrays: Kh,Kl,Vh,Vl][64][KSTR] bf16 = 73728 B.
// ===========================================================================
#define KSTR 72
#define A_ARR (64 * KSTR)
#define A_STG (4 * A_ARR)
#define ATTN_SMEM (2 * A_STG * 2)

__global__ __launch_bounds__(128) void attn_kernel(float* __restrict__ out)
{
    extern __shared__ __nv_bfloat16 SM[];
    const uint32_t smb = smem_u32(SM);

    const int b = blockIdx.y;
    const int qt0 = (int)(gridDim.x - 1 - blockIdx.x) * 64;   // longest first
    const int tid = threadIdx.x;
    const int wid = tid >> 5, lane = tid & 31;
    const int g = lane >> 2, tig = lane & 3;
    const int row_base = qt0 + wid * 16;

    const __nv_bfloat16* qhp = g_qh + (size_t)b * T_ * H_;
    const __nv_bfloat16* qlp = g_ql + (size_t)b * T_ * H_;
    const __nv_bfloat16* khp = g_kh + (size_t)b * T_ * H_;
    const __nv_bfloat16* klp = g_kl + (size_t)b * T_ * H_;
    const __nv_bfloat16* vhp = g_vh + (size_t)b * T_ * H_;
    const __nv_bfloat16* vlp = g_vl + (size_t)b * T_ * H_;

    // Q fragments (4 k16 slices, hi + lo).
    uint32_t qh[4][4], ql[4][4];
#pragma unroll
    for (int ks = 0; ks < 4; ks++) {
        int c0 = ks * 16 + 2 * tig;
        size_t r0 = (size_t)(row_base + g) * H_;
        size_t r1 = (size_t)(row_base + g + 8) * H_;
        qh[ks][0] = *reinterpret_cast<const uint32_t*>(qhp + r0 + c0);
        qh[ks][1] = *reinterpret_cast<const uint32_t*>(qhp + r1 + c0);
        qh[ks][2] = *reinterpret_cast<const uint32_t*>(qhp + r0 + c0 + 8);
        qh[ks][3] = *reinterpret_cast<const uint32_t*>(qhp + r1 + c0 + 8);
        ql[ks][0] = *reinterpret_cast<const uint32_t*>(qlp + r0 + c0);
        ql[ks][1] = *reinterpret_cast<const uint32_t*>(qlp + r1 + c0);
        ql[ks][2] = *reinterpret_cast<const uint32_t*>(qlp + r0 + c0 + 8);
        ql[ks][3] = *reinterpret_cast<const uint32_t*>(qlp + r1 + c0 + 8);
    }

    float oacc[8][4];
#pragma unroll
    for (int nt = 0; nt < 8; nt++)
#pragma unroll
        for (int i = 0; i < 4; i++) oacc[nt][i] = 0.f;
    float m0 = -1e30f, m1 = -1e30f, l0 = 0.f, l1 = 0.f;

    const int lm15 = lane & 15;

    auto prefetch = [&](int s0, int stg) {
        const __nv_bfloat16* srcs[4] = {khp, klp, vhp, vlp};
#pragma unroll
        for (int arr = 0; arr < 4; arr++) {
#pragma unroll
            for (int i = 0; i < 4; i++) {
                int idx = tid + i * 128;           // 0..511
                int row = idx >> 3, qc = idx & 7;
                uint32_t dst = smb +
                    (uint32_t)(stg * A_STG + arr * A_ARR + row * KSTR + qc * 8) * 2;
                CP_ASYNC16(dst, srcs[arr] + (size_t)(s0 + row) * H_ + qc * 8);
            }
        }
    };

    const int ntiles = qt0 / 64 + 1;
    prefetch(0, 0);
    CP_COMMIT();

    for (int it = 0; it < ntiles; it++) {
        const int s = it & 1;
        const int s0 = it * 64;
        if (it + 1 < ntiles) {
            prefetch((it + 1) * 64, s ^ 1);
            CP_COMMIT();
            CP_WAIT1();
        } else {
            CP_WAIT0();
        }
        __syncthreads();

        const __nv_bfloat16* Ksh = SM + s * A_STG;
        const __nv_bfloat16* Ksl = Ksh + A_ARR;
        const uint32_t vsh0 = smb + (uint32_t)(s * A_STG + 2 * A_ARR) * 2;
        const uint32_t vsl0 = smb + (uint32_t)(s * A_STG + 3 * A_ARR) * 2;

        // ---- S = Q K^T ----
        float sacc[8][4];
#pragma unroll
        for (int nt = 0; nt < 8; nt++) {
            sacc[nt][0] = 0.f; sacc[nt][1] = 0.f;
            sacc[nt][2] = 0.f; sacc[nt][3] = 0.f;
#pragma unroll
            for (int ks = 0; ks < 4; ks++) {
                int c0 = ks * 16 + 2 * tig;
                uint32_t bh[2], bl[2];
                bh[0] = *reinterpret_cast<const uint32_t*>(Ksh + (nt * 8 + g) * KSTR + c0);
                bh[1] = *reinterpret_cast<const uint32_t*>(Ksh + (nt * 8 + g) * KSTR + c0 + 8);
                bl[0] = *reinterpret_cast<const uint32_t*>(Ksl + (nt * 8 + g) * KSTR + c0);
                bl[1] = *reinterpret_cast<const uint32_t*>(Ksl + (nt * 8 + g) * KSTR + c0 + 8);
                mma_bf16(sacc[nt], qh[ks], bh);
                mma_bf16(sacc[nt], qh[ks], bl);
                mma_bf16(sacc[nt], ql[ks], bh);
            }
        }

        // ---- causal mask (diagonal tile only) ----
        if (it == ntiles - 1) {
            const int r0 = row_base + g, r1 = r0 + 8;
#pragma unroll
            for (int nt = 0; nt < 8; nt++) {
                int c = s0 + nt * 8 + 2 * tig;
                if (c > r0)     sacc[nt][0] = -1e30f;
                if (c + 1 > r0) sacc[nt][1] = -1e30f;
                if (c > r1)     sacc[nt][2] = -1e30f;
                if (c + 1 > r1) sacc[nt][3] = -1e30f;
            }
        }

        // ---- online softmax ----
        float rm0 = -1e30f, rm1 = -1e30f;
#pragma unroll
        for (int nt = 0; nt < 8; nt++) {
            rm0 = fmaxf(rm0, fmaxf(sacc[nt][0], sacc[nt][1]));
            rm1 = fmaxf(rm1, fmaxf(sacc[nt][2], sacc[nt][3]));
        }
        rm0 = fmaxf(rm0, __shfl_xor_sync(0xffffffffu, rm0, 1));
        rm0 = fmaxf(rm0, __shfl_xor_sync(0xffffffffu, rm0, 2));
        rm1 = fmaxf(rm1, __shfl_xor_sync(0xffffffffu, rm1, 1));
        rm1 = fmaxf(rm1, __shfl_xor_sync(0xffffffffu, rm1, 2));
        const float nm0 = fmaxf(m0, rm0), nm1 = fmaxf(m1, rm1);
        const float a0 = __expf(m0 - nm0), a1 = __expf(m1 - nm1);
        m0 = nm0; m1 = nm1;

        float ps0 = 0.f, ps1 = 0.f;
#pragma unroll
        for (int nt = 0; nt < 8; nt++) {
            sacc[nt][0] = __expf(sacc[nt][0] - nm0);
            sacc[nt][1] = __expf(sacc[nt][1] - nm0);
            sacc[nt][2] = __expf(sacc[nt][2] - nm1);
            sacc[nt][3] = __expf(sacc[nt][3] - nm1);
            ps0 += sacc[nt][0] + sacc[nt][1];
            ps1 += sacc[nt][2] + sacc[nt][3];
        }
        ps0 += __shfl_xor_sync(0xffffffffu, ps0, 1);
        ps0 += __shfl_xor_sync(0xffffffffu, ps0, 2);
        ps1 += __shfl_xor_sync(0xffffffffu, ps1, 1);
        ps1 += __shfl_xor_sync(0xffffffffu, ps1, 2);
        l0 = l0 * a0 + ps0;
        l1 = l1 * a1 + ps1;
#pragma unroll
        for (int nt = 0; nt < 8; nt++) {
            oacc[nt][0] *= a0; oacc[nt][1] *= a0;
            oacc[nt][2] *= a1; oacc[nt][3] *= a1;
        }

        // ---- O += P V ----
#pragma unroll
        for (int ks = 0; ks < 4; ks++) {
            uint32_t ph[4], pl[4];
            split_pair(sacc[2 * ks][0],     sacc[2 * ks][1],     ph[0], pl[0]);
            split_pair(sacc[2 * ks][2],     sacc[2 * ks][3],     ph[1], pl[1]);
            split_pair(sacc[2 * ks + 1][0], sacc[2 * ks + 1][1], ph[2], pl[2]);
            split_pair(sacc[2 * ks + 1][2], sacc[2 * ks + 1][3], ph[3], pl[3]);
            const uint32_t rowoff = (uint32_t)((ks * 16 + lm15) * KSTR) * 2u;
#pragma unroll
            for (int nt = 0; nt < 8; nt++) {
                uint32_t bh[2], bl[2];
                ldsm_x2_trans(bh[0], bh[1], vsh0 + rowoff + (uint32_t)(nt * 16));
                ldsm_x2_trans(bl[0], bl[1], vsl0 + rowoff + (uint32_t)(nt * 16));
                mma_bf16(oacc[nt], ph, bh);
                mma_bf16(oacc[nt], ph, bl);
                mma_bf16(oacc[nt], pl, bh);
            }
        }
        __syncthreads();
    }

    // ---- epilogue ----
    const float inv0 = 1.f / l0, inv1 = 1.f / l1;
    float* orow0 = out + ((size_t)b * T_ + row_base + g) * H_;
    float* orow1 = out + ((size_t)b * T_ + row_base + g + 8) * H_;
#pragma unroll
    for (int nt = 0; nt < 8; nt++) {
        int c = nt * 8 + 2 * tig;
        float2 v0 = make_float2(oacc[nt][0] * inv0, oacc[nt][1] * inv0);
        float2 v1 = make_float2(oacc[nt][2] * inv1, oacc[nt][3] * inv1);
        *reinterpret_cast<float2*>(orow0 + c) = v0;
        *reinterpret_cast<float2*>(orow1 + c) = v1;
    }
}

// ===========================================================================
extern "C" void kernel_launch(void* const* d_in, const int* in_sizes, int n_in,
                              void* d_out, int out_size)
{
    const float* x  = (const float*)d_in[0];
    const float* Wq = (const float*)d_in[1];
    const float* Wk = (const float*)d_in[2];
    const float* Wv = (const float*)d_in[3];
    float* out = (float*)d_out;

    cudaFuncSetAttribute(proj_kernel,
        cudaFuncAttributeMaxDynamicSharedMemorySize, PROJ_SMEM);
    cudaFuncSetAttribute(attn_kernel,
        cudaFuncAttributeMaxDynamicSharedMemorySize, ATTN_SMEM);

    split_w_kernel<<<192, 256>>>(Wq, Wk, Wv);
    proj_kernel<<<(B_ * T_) / 64, 384, PROJ_SMEM>>>(x);

    dim3 gattn(T_ / 64, B_);
    attn_kernel<<<gattn, 128, ATTN_SMEM>>>(out);
}

// round 7
// speedup vs baseline: 4.2563x; 1.3181x over previous
#include <cuda_runtime.h>
#include <cuda_bf16.h>
#include <cstdint>

#define B_  16
#define T_  2048
#define C_  1024
#define H_  64

// q/k/v stored pre-split as bf16 hi/lo pairs.
__device__ __nv_bfloat16 g_qh[(size_t)B_ * T_ * H_];
__device__ __nv_bfloat16 g_ql[(size_t)B_ * T_ * H_];
__device__ __nv_bfloat16 g_kh[(size_t)B_ * T_ * H_];
__device__ __nv_bfloat16 g_kl[(size_t)B_ * T_ * H_];
__device__ __nv_bfloat16 g_vh[(size_t)B_ * T_ * H_];
__device__ __nv_bfloat16 g_vl[(size_t)B_ * T_ * H_];

// W pre-split + transposed: row n = mat*64 + h (0..191), col k (0..1023).
__device__ __nv_bfloat16 g_wh[192 * C_];
__device__ __nv_bfloat16 g_wl[192 * C_];

// ---------------------------------------------------------------------------
__device__ __forceinline__ void mma_bf16(float* d, const uint32_t* a,
                                         const uint32_t* b) {
    asm volatile(
        "mma.sync.aligned.m16n8k16.row.col.f32.bf16.bf16.f32 "
        "{%0,%1,%2,%3}, {%4,%5,%6,%7}, {%8,%9}, {%0,%1,%2,%3};"
        : "+f"(d[0]), "+f"(d[1]), "+f"(d[2]), "+f"(d[3])
        : "r"(a[0]), "r"(a[1]), "r"(a[2]), "r"(a[3]), "r"(b[0]), "r"(b[1]));
}

__device__ __forceinline__ void ldsm_x2_trans(uint32_t& r0, uint32_t& r1,
                                              uint32_t addr) {
    asm volatile("ldmatrix.sync.aligned.m8n8.x2.trans.shared.b16 {%0,%1}, [%2];"
                 : "=r"(r0), "=r"(r1) : "r"(addr));
}

__device__ __forceinline__ uint32_t smem_u32(const void* p) {
    uint32_t a;
    asm("{ .reg .u64 t; cvta.to.shared.u64 t, %1; cvt.u32.u64 %0, t; }"
        : "=r"(a) : "l"(p));
    return a;
}

#define CP_ASYNC16(dst, src) \
    asm volatile("cp.async.cg.shared.global [%0], [%1], 16;" \
                 :: "r"(dst), "l"(src) : "memory")
#define CP_COMMIT() asm volatile("cp.async.commit_group;" ::: "memory")
#define CP_WAIT0()  asm volatile("cp.async.wait_group 0;" ::: "memory")
#define CP_WAIT1()  asm volatile("cp.async.wait_group 1;" ::: "memory")

__device__ __forceinline__ void split_pair(float x, float y,
                                           uint32_t& hi, uint32_t& lo) {
    __nv_bfloat16 hx = __float2bfloat16(x);
    __nv_bfloat16 hy = __float2bfloat16(y);
    __nv_bfloat162 hv(hx, hy);
    hi = *reinterpret_cast<uint32_t*>(&hv);
    __nv_bfloat162 lv = __floats2bfloat162_rn(x - __bfloat162float(hx),
                                              y - __bfloat162float(hy));
    lo = *reinterpret_cast<uint32_t*>(&lv);
}

// ===========================================================================
// Kernel 0: one-time W split/transpose.
// ===========================================================================
__global__ __launch_bounds__(256) void split_w_kernel(
    const float* __restrict__ Wq,
    const float* __restrict__ Wk,
    const float* __restrict__ Wv)
{
    const int n = blockIdx.x;             // 0..191
    const int mat = n >> 6;
    const int h = n & 63;
    const float* W = (mat == 0) ? Wq : (mat == 1) ? Wk : Wv;
    const float s = (mat == 0) ? 0.125f : 1.0f;

    for (int k = threadIdx.x; k < C_; k += 256) {
        float v = W[(size_t)k * H_ + h] * s;
        __nv_bfloat16 hb = __float2bfloat16(v);
        g_wh[(size_t)n * C_ + k] = hb;
        g_wl[(size_t)n * C_ + k] = __float2bfloat16(v - __bfloat162float(hb));
    }
}

// ===========================================================================
// Kernel 1: QKV projection. BM=128, N=192, BK=32, 384 threads:
// 4 m-warps x 3 n-warps; each warp: 2 m16 x 8 n8 tiles, hi/lo split x3.
// cp.async double-buffered W; X split in-register. 100 KB dyn smem.
// ===========================================================================
#define PSTR 40
#define PX (128 * PSTR)              // 5120 elems per X stage
#define PW (192 * PSTR)              // 7680 elems per W stage
#define XH_OFF 0
#define XL_OFF (2 * PX)              // 10240
#define WH_OFF (4 * PX)              // 20480
#define WL_OFF (WH_OFF + 2 * PW)     // 35840
#define PROJ_SMEM ((WL_OFF + 2 * PW) * 2)   // 102400 bytes

__global__ __launch_bounds__(384) void proj_kernel(const float* __restrict__ x)
{
    extern __shared__ __nv_bfloat16 SM[];
    const uint32_t smb = smem_u32(SM);

    const int tid = threadIdx.x;
    const int wid = tid >> 5, lane = tid & 31;
    const int g = lane >> 2, tig = lane & 3;
    const int wm = wid & 3;          // 0..3 : 32-row band
    const int wn = wid >> 2;         // 0..2 : 64-col band = one matrix
    const int row0 = blockIdx.x * 128;

    float acc[2][8][4];
#pragma unroll
    for (int mt = 0; mt < 2; mt++)
#pragma unroll
        for (int nt = 0; nt < 8; nt++)
#pragma unroll
            for (int i = 0; i < 4; i++) acc[mt][nt][i] = 0.f;

    float4 xv[3];

    auto x_load = [&](int k0) {
#pragma unroll
        for (int j = 0; j < 3; j++) {
            int idx = tid + j * 384;
            if (idx < 1024) {
                int m = idx >> 3, f4 = idx & 7;
                xv[j] = *reinterpret_cast<const float4*>(
                    x + (size_t)(row0 + m) * C_ + k0 + f4 * 4);
            }
        }
    };
    auto x_store = [&](int stg) {
        __nv_bfloat16* Xh = SM + XH_OFF + stg * PX;
        __nv_bfloat16* Xl = SM + XL_OFF + stg * PX;
#pragma unroll
        for (int j = 0; j < 3; j++) {
            int idx = tid + j * 384;
            if (idx < 1024) {
                int m = idx >> 3, f4 = idx & 7;
                int o = m * PSTR + f4 * 4;
                uint32_t h0, l0, h1, l1;
                split_pair(xv[j].x, xv[j].y, h0, l0);
                split_pair(xv[j].z, xv[j].w, h1, l1);
                *reinterpret_cast<uint32_t*>(Xh + o)     = h0;
                *reinterpret_cast<uint32_t*>(Xh + o + 2) = h1;
                *reinterpret_cast<uint32_t*>(Xl + o)     = l0;
                *reinterpret_cast<uint32_t*>(Xl + o + 2) = l1;
            }
        }
    };
    auto w_prefetch = [&](int k0, int stg) {
#pragma unroll
        for (int j = 0; j < 2; j++) {
            int i = tid + j * 384;
            int n = i >> 2, q = i & 3;
            uint32_t dh = smb + (uint32_t)(WH_OFF + stg * PW + n * PSTR + q * 8) * 2;
            uint32_t dl = smb + (uint32_t)(WL_OFF + stg * PW + n * PSTR + q * 8) * 2;
            CP_ASYNC16(dh, g_wh + (size_t)n * C_ + k0 + q * 8);
            CP_ASYNC16(dl, g_wl + (size_t)n * C_ + k0 + q * 8);
        }
    };

    // Prologue: chunk 0 into stage 0.
    x_load(0);
    w_prefetch(0, 0);
    CP_COMMIT();
    x_store(0);
    CP_WAIT0();
    __syncthreads();

    for (int ch = 0; ch < 32; ch++) {
        const int s = ch & 1;
        if (ch < 31) {
            x_load((ch + 1) * 32);
            w_prefetch((ch + 1) * 32, s ^ 1);
            CP_COMMIT();
        }

        const __nv_bfloat16* Xh = SM + XH_OFF + s * PX;
        const __nv_bfloat16* Xl = SM + XL_OFF + s * PX;
        const __nv_bfloat16* Wh = SM + WH_OFF + s * PW;
        const __nv_bfloat16* Wl = SM + WL_OFF + s * PW;
#pragma unroll
        for (int ks = 0; ks < 2; ks++) {
            const int c0 = ks * 16 + 2 * tig;
            uint32_t ah[2][4], al[2][4];
#pragma unroll
            for (int mt = 0; mt < 2; mt++) {
                int rm = wm * 32 + mt * 16;
                ah[mt][0] = *reinterpret_cast<const uint32_t*>(Xh + (rm + g) * PSTR + c0);
                ah[mt][1] = *reinterpret_cast<const uint32_t*>(Xh + (rm + g + 8) * PSTR + c0);
                ah[mt][2] = *reinterpret_cast<const uint32_t*>(Xh + (rm + g) * PSTR + c0 + 8);
                ah[mt][3] = *reinterpret_cast<const uint32_t*>(Xh + (rm + g + 8) * PSTR + c0 + 8);
                al[mt][0] = *reinterpret_cast<const uint32_t*>(Xl + (rm + g) * PSTR + c0);
                al[mt][1] = *reinterpret_cast<const uint32_t*>(Xl + (rm + g + 8) * PSTR + c0);
                al[mt][2] = *reinterpret_cast<const uint32_t*>(Xl + (rm + g) * PSTR + c0 + 8);
                al[mt][3] = *reinterpret_cast<const uint32_t*>(Xl + (rm + g + 8) * PSTR + c0 + 8);
            }
#pragma unroll
            for (int nt = 0; nt < 8; nt++) {
                int nb = wn * 64 + nt * 8;
                uint32_t bh[2], bl[2];
                bh[0] = *reinterpret_cast<const uint32_t*>(Wh + (nb + g) * PSTR + c0);
                bh[1] = *reinterpret_cast<const uint32_t*>(Wh + (nb + g) * PSTR + c0 + 8);
                bl[0] = *reinterpret_cast<const uint32_t*>(Wl + (nb + g) * PSTR + c0);
                bl[1] = *reinterpret_cast<const uint32_t*>(Wl + (nb + g) * PSTR + c0 + 8);
#pragma unroll
                for (int mt = 0; mt < 2; mt++) {
                    mma_bf16(acc[mt][nt], ah[mt], bh);
                    mma_bf16(acc[mt][nt], ah[mt], bl);
                    mma_bf16(acc[mt][nt], al[mt], bh);
                }
            }
        }

        if (ch < 31) {
            x_store(s ^ 1);
            CP_WAIT0();
        }
        __syncthreads();
    }

    // Epilogue: warp's 64-col band IS one matrix (mat = wn).
    __nv_bfloat16* outh = (wn == 0) ? g_qh : (wn == 1) ? g_kh : g_vh;
    __nv_bfloat16* outl = (wn == 0) ? g_ql : (wn == 1) ? g_kl : g_vl;
#pragma unroll
    for (int mt = 0; mt < 2; mt++)
#pragma unroll
        for (int nt = 0; nt < 8; nt++) {
            int r0 = row0 + wm * 32 + mt * 16 + g;
            int h = nt * 8 + 2 * tig;
            uint32_t hi, lo;
            split_pair(acc[mt][nt][0], acc[mt][nt][1], hi, lo);
            *reinterpret_cast<uint32_t*>(outh + (size_t)r0 * H_ + h) = hi;
            *reinterpret_cast<uint32_t*>(outl + (size_t)r0 * H_ + h) = lo;
            split_pair(acc[mt][nt][2], acc[mt][nt][3], hi, lo);
            *reinterpret_cast<uint32_t*>(outh + (size_t)(r0 + 8) * H_ + h) = hi;
            *reinterpret_cast<uint32_t*>(outl + (size_t)(r0 + 8) * H_ + h) = lo;
        }
}

// ===========================================================================
// Kernel 2: causal flash attention. BM=64 (4 warps), min 3 blocks/SM,
// cp.async double-buffered KV tiles (64 keys).
// ===========================================================================
#define KSTR 72
#define A_ARR (64 * KSTR)
#define A_STG (4 * A_ARR)
#define ATTN_SMEM (2 * A_STG * 2)    // 73728 B; 3 blocks/SM = 216 KB

__global__ __launch_bounds__(128, 3) void attn_kernel(float* __restrict__ out)
{
    extern __shared__ __nv_bfloat16 SM[];
    const uint32_t smb = smem_u32(SM);

    const int b = blockIdx.y;
    const int qt0 = (int)(gridDim.x - 1 - blockIdx.x) * 64;   // longest first
    const int tid = threadIdx.x;
    const int wid = tid >> 5, lane = tid & 31;
    const int g = lane >> 2, tig = lane & 3;
    const int row_base = qt0 + wid * 16;

    const __nv_bfloat16* qhp = g_qh + (size_t)b * T_ * H_;
    const __nv_bfloat16* qlp = g_ql + (size_t)b * T_ * H_;
    const __nv_bfloat16* khp = g_kh + (size_t)b * T_ * H_;
    const __nv_bfloat16* klp = g_kl + (size_t)b * T_ * H_;
    const __nv_bfloat16* vhp = g_vh + (size_t)b * T_ * H_;
    const __nv_bfloat16* vlp = g_vl + (size_t)b * T_ * H_;

    uint32_t qh[4][4], ql[4][4];
#pragma unroll
    for (int ks = 0; ks < 4; ks++) {
        int c0 = ks * 16 + 2 * tig;
        size_t r0 = (size_t)(row_base + g) * H_;
        size_t r1 = (size_t)(row_base + g + 8) * H_;
        qh[ks][0] = *reinterpret_cast<const uint32_t*>(qhp + r0 + c0);
        qh[ks][1] = *reinterpret_cast<const uint32_t*>(qhp + r1 + c0);
        qh[ks][2] = *reinterpret_cast<const uint32_t*>(qhp + r0 + c0 + 8);
        qh[ks][3] = *reinterpret_cast<const uint32_t*>(qhp + r1 + c0 + 8);
        ql[ks][0] = *reinterpret_cast<const uint32_t*>(qlp + r0 + c0);
        ql[ks][1] = *reinterpret_cast<const uint32_t*>(qlp + r1 + c0);
        ql[ks][2] = *reinterpret_cast<const uint32_t*>(qlp + r0 + c0 + 8);
        ql[ks][3] = *reinterpret_cast<const uint32_t*>(qlp + r1 + c0 + 8);
    }

    float oacc[8][4];
#pragma unroll
    for (int nt = 0; nt < 8; nt++)
#pragma unroll
        for (int i = 0; i < 4; i++) oacc[nt][i] = 0.f;
    float m0 = -1e30f, m1 = -1e30f, l0 = 0.f, l1 = 0.f;

    const int lm15 = lane & 15;

    auto prefetch = [&](int s0, int stg) {
        const __nv_bfloat16* srcs[4] = {khp, klp, vhp, vlp};
#pragma unroll
        for (int arr = 0; arr < 4; arr++) {
#pragma unroll
            for (int i = 0; i < 4; i++) {
                int idx = tid + i * 128;
                int row = idx >> 3, qc = idx & 7;
                uint32_t dst = smb +
                    (uint32_t)(stg * A_STG + arr * A_ARR + row * KSTR + qc * 8) * 2;
                CP_ASYNC16(dst, srcs[arr] + (size_t)(s0 + row) * H_ + qc * 8);
            }
        }
    };

    const int ntiles = qt0 / 64 + 1;
    prefetch(0, 0);
    CP_COMMIT();

    for (int it = 0; it < ntiles; it++) {
        const int s = it & 1;
        const int s0 = it * 64;
        if (it + 1 < ntiles) {
            prefetch((it + 1) * 64, s ^ 1);
            CP_COMMIT();
            CP_WAIT1();
        } else {
            CP_WAIT0();
        }
        __syncthreads();

        const __nv_bfloat16* Ksh = SM + s * A_STG;
        const __nv_bfloat16* Ksl = Ksh + A_ARR;
        const uint32_t vsh0 = smb + (uint32_t)(s * A_STG + 2 * A_ARR) * 2;
        const uint32_t vsl0 = smb + (uint32_t)(s * A_STG + 3 * A_ARR) * 2;

        // ---- S = Q K^T (ks outer -> 8 independent chains per step) ----
        float sacc[8][4];
#pragma unroll
        for (int nt = 0; nt < 8; nt++) {
            sacc[nt][0] = 0.f; sacc[nt][1] = 0.f;
            sacc[nt][2] = 0.f; sacc[nt][3] = 0.f;
        }
#pragma unroll
        for (int ks = 0; ks < 4; ks++) {
            const int c0 = ks * 16 + 2 * tig;
#pragma unroll
            for (int nt = 0; nt < 8; nt++) {
                uint32_t bh[2], bl[2];
                bh[0] = *reinterpret_cast<const uint32_t*>(Ksh + (nt * 8 + g) * KSTR + c0);
                bh[1] = *reinterpret_cast<const uint32_t*>(Ksh + (nt * 8 + g) * KSTR + c0 + 8);
                bl[0] = *reinterpret_cast<const uint32_t*>(Ksl + (nt * 8 + g) * KSTR + c0);
                bl[1] = *reinterpret_cast<const uint32_t*>(Ksl + (nt * 8 + g) * KSTR + c0 + 8);
                mma_bf16(sacc[nt], qh[ks], bh);
                mma_bf16(sacc[nt], qh[ks], bl);
                mma_bf16(sacc[nt], ql[ks], bh);
            }
        }

        // ---- causal mask (diagonal tile only) ----
        if (it == ntiles - 1) {
            const int r0 = row_base + g, r1 = r0 + 8;
#pragma unroll
            for (int nt = 0; nt < 8; nt++) {
                int c = s0 + nt * 8 + 2 * tig;
                if (c > r0)     sacc[nt][0] = -1e30f;
                if (c + 1 > r0) sacc[nt][1] = -1e30f;
                if (c > r1)     sacc[nt][2] = -1e30f;
                if (c + 1 > r1) sacc[nt][3] = -1e30f;
            }
        }

        // ---- online softmax ----
        float rm0 = -1e30f, rm1 = -1e30f;
#pragma unroll
        for (int nt = 0; nt < 8; nt++) {
            rm0 = fmaxf(rm0, fmaxf(sacc[nt][0], sacc[nt][1]));
            rm1 = fmaxf(rm1, fmaxf(sacc[nt][2], sacc[nt][3]));
        }
        rm0 = fmaxf(rm0, __shfl_xor_sync(0xffffffffu, rm0, 1));
        rm0 = fmaxf(rm0, __shfl_xor_sync(0xffffffffu, rm0, 2));
        rm1 = fmaxf(rm1, __shfl_xor_sync(0xffffffffu, rm1, 1));
        rm1 = fmaxf(rm1, __shfl_xor_sync(0xffffffffu, rm1, 2));
        const float nm0 = fmaxf(m0, rm0), nm1 = fmaxf(m1, rm1);
        const float a0 = __expf(m0 - nm0), a1 = __expf(m1 - nm1);
        m0 = nm0; m1 = nm1;

        float ps0 = 0.f, ps1 = 0.f;
#pragma unroll
        for (int nt = 0; nt < 8; nt++) {
            sacc[nt][0] = __expf(sacc[nt][0] - nm0);
            sacc[nt][1] = __expf(sacc[nt][1] - nm0);
            sacc[nt][2] = __expf(sacc[nt][2] - nm1);
            sacc[nt][3] = __expf(sacc[nt][3] - nm1);
            ps0 += sacc[nt][0] + sacc[nt][1];
            ps1 += sacc[nt][2] + sacc[nt][3];
        }
        ps0 += __shfl_xor_sync(0xffffffffu, ps0, 1);
        ps0 += __shfl_xor_sync(0xffffffffu, ps0, 2);
        ps1 += __shfl_xor_sync(0xffffffffu, ps1, 1);
        ps1 += __shfl_xor_sync(0xffffffffu, ps1, 2);
        l0 = l0 * a0 + ps0;
        l1 = l1 * a1 + ps1;
#pragma unroll
        for (int nt = 0; nt < 8; nt++) {
            oacc[nt][0] *= a0; oacc[nt][1] *= a0;
            oacc[nt][2] *= a1; oacc[nt][3] *= a1;
        }

        // ---- O += P V ----
#pragma unroll
        for (int ks = 0; ks < 4; ks++) {
            uint32_t ph[4], pl[4];
            split_pair(sacc[2 * ks][0],     sacc[2 * ks][1],     ph[0], pl[0]);
            split_pair(sacc[2 * ks][2],     sacc[2 * ks][3],     ph[1], pl[1]);
            split_pair(sacc[2 * ks + 1][0], sacc[2 * ks + 1][1], ph[2], pl[2]);
            split_pair(sacc[2 * ks + 1][2], sacc[2 * ks + 1][3], ph[3], pl[3]);
            const uint32_t rowoff = (uint32_t)((ks * 16 + lm15) * KSTR) * 2u;
#pragma unroll
            for (int nt = 0; nt < 8; nt++) {
                uint32_t bh[2], bl[2];
                ldsm_x2_trans(bh[0], bh[1], vsh0 + rowoff + (uint32_t)(nt * 16));
                ldsm_x2_trans(bl[0], bl[1], vsl0 + rowoff + (uint32_t)(nt * 16));
                mma_bf16(oacc[nt], ph, bh);
                mma_bf16(oacc[nt], ph, bl);
                mma_bf16(oacc[nt], pl, bh);
            }
        }
        __syncthreads();
    }

    // ---- epilogue ----
    const float inv0 = 1.f / l0, inv1 = 1.f / l1;
    float* orow0 = out + ((size_t)b * T_ + row_base + g) * H_;
    float* orow1 = out + ((size_t)b * T_ + row_base + g + 8) * H_;
#pragma unroll
    for (int nt = 0; nt < 8; nt++) {
        int c = nt * 8 + 2 * tig;
        float2 v0 = make_float2(oacc[nt][0] * inv0, oacc[nt][1] * inv0);
        float2 v1 = make_float2(oacc[nt][2] * inv1, oacc[nt][3] * inv1);
        *reinterpret_cast<float2*>(orow0 + c) = v0;
        *reinterpret_cast<float2*>(orow1 + c) = v1;
    }
}

// ===========================================================================
extern "C" void kernel_launch(void* const* d_in, const int* in_sizes, int n_in,
                              void* d_out, int out_size)
{
    const float* x  = (const float*)d_in[0];
    const float* Wq = (const float*)d_in[1];
    const float* Wk = (const float*)d_in[2];
    const float* Wv = (const float*)d_in[3];
    float* out = (float*)d_out;

    cudaFuncSetAttribute(proj_kernel,
        cudaFuncAttributeMaxDynamicSharedMemorySize, PROJ_SMEM);
    cudaFuncSetAttribute(attn_kernel,
        cudaFuncAttributeMaxDynamicSharedMemorySize, ATTN_SMEM);

    split_w_kernel<<<192, 256>>>(Wq, Wk, Wv);
    proj_kernel<<<(B_ * T_) / 128, 384, PROJ_SMEM>>>(x);

    dim3 gattn(T_ / 64, B_);
    attn_kernel<<<gattn, 128, ATTN_SMEM>>>(out);
}